// round 13
// baseline (speedup 1.0000x reference)
#include <cuda_runtime.h>
#include <cuda_bf16.h>
#include <math.h>
#include <stdint.h>

#define Bb 32
#define Nn 4096
#define Dd 256
#define Kk 128
#define Dc 64

// ---------------- device scratch ----------------
__device__ float g_agg[(size_t)Bb * Kk * Dc];
__device__ float g_mass[Bb * Kk];
__device__ float g_ss[Bb];

// ---------------- smem word-offset layout (32-bit words) ----------------
#define OFF_XH   0        // X hi  [128 tok][132]
#define OFF_XL   16896
#define OFF_WC_H 33792    // W chunk hi [192 row][36]
#define OFF_WC_L 40704
#define OFF_Y    0        // Y fp32 col-major [192 col][132 tok]
#define OFF_AT_H 25344    // assign^T hi [128 cl][68]
#define OFF_AT_L 34048
#define OFF_H_H  42752    // h hi [128 tok][36]
#define OFF_H_L  47360
#define OFF_SQ_H 42752    // sq^T hi [72 d][68] (aliases h after stage 2)
#define OFF_SQ_L 47648
#define OFF_W2_H 52544    // W2 hi [64 f][36]
#define OFF_W2_L 54848
#define SMEM_WORDS 57152  // 228608 bytes

// ---------------- helpers ----------------
__device__ __forceinline__ void split2(float x, unsigned short& h, unsigned short& l) {
    __nv_bfloat16 hb = __float2bfloat16_rn(x);
    float lf = x - __bfloat162float(hb);
    h = __bfloat16_as_ushort(hb);
    l = __bfloat16_as_ushort(__float2bfloat16_rn(lf));
}
__device__ __forceinline__ void pack8(const float* v, uint4& H, uint4& L) {
    unsigned short h[8], l[8];
    #pragma unroll
    for (int i = 0; i < 8; i++) split2(v[i], h[i], l[i]);
    H.x = (uint32_t)h[0] | ((uint32_t)h[1] << 16);
    H.y = (uint32_t)h[2] | ((uint32_t)h[3] << 16);
    H.z = (uint32_t)h[4] | ((uint32_t)h[5] << 16);
    H.w = (uint32_t)h[6] | ((uint32_t)h[7] << 16);
    L.x = (uint32_t)l[0] | ((uint32_t)l[1] << 16);
    L.y = (uint32_t)l[2] | ((uint32_t)l[3] << 16);
    L.z = (uint32_t)l[4] | ((uint32_t)l[5] << 16);
    L.w = (uint32_t)l[6] | ((uint32_t)l[7] << 16);
}
__device__ __forceinline__ void mma16(float* d, const uint32_t* a, const uint32_t* b) {
    asm volatile(
        "mma.sync.aligned.m16n8k16.row.col.f32.bf16.bf16.f32 "
        "{%0,%1,%2,%3}, {%4,%5,%6,%7}, {%8,%9}, {%0,%1,%2,%3};"
        : "+f"(d[0]), "+f"(d[1]), "+f"(d[2]), "+f"(d[3])
        : "r"(a[0]), "r"(a[1]), "r"(a[2]), "r"(a[3]), "r"(b[0]), "r"(b[1]));
}
__device__ __forceinline__ void st16s(uint32_t* smu, int word, int half, unsigned short v) {
    ((unsigned short*)&smu[word])[half] = v;
}
__device__ __forceinline__ uint32_t sptr(const void* p) {
    return (uint32_t)__cvta_generic_to_shared(p);
}
#define LDSM4(R0, R1, R2, R3, A) \
    asm volatile("ldmatrix.sync.aligned.m8n8.x4.shared.b16 {%0,%1,%2,%3}, [%4];" \
                 : "=r"(R0), "=r"(R1), "=r"(R2), "=r"(R3) : "r"(A))
#define LDSM2(R0, R1, A) \
    asm volatile("ldmatrix.sync.aligned.m8n8.x2.shared.b16 {%0,%1}, [%2];" \
                 : "=r"(R0), "=r"(R1) : "r"(A))

// ---------------- init ----------------
__global__ void __launch_bounds__(256) k_init() {
    int i = blockIdx.x * 256 + threadIdx.x;
    if (i < Bb * Kk * Dc) g_agg[i] = 0.0f;
    else if (i < Bb * Kk * Dc + Bb * Kk) g_mass[i - Bb * Kk * Dc] = 0.0f;
    else if (i < Bb * Kk * Dc + Bb * Kk + Bb) g_ss[i - Bb * Kk * Dc - Bb * Kk] = 0.0f;
}

// ---------------- fused main kernel: one 128-token tile per block, 512 threads ----------------
__global__ void __launch_bounds__(512, 1) k_fused(
    const float* __restrict__ X,  const float* __restrict__ W1,
    const float* __restrict__ b1, const float* __restrict__ W2,
    const float* __restrict__ b2, const float* __restrict__ Wa,
    const float* __restrict__ ba)
{
    extern __shared__ float smf[];
    uint32_t* smu = (uint32_t*)smf;
    __shared__ float s_ba[128], s_b1[64], s_b2[64];

    const int tid  = threadIdx.x;
    const int w    = tid >> 5;          // 0..15
    const int lane = tid & 31;
    const int ty   = lane >> 2;
    const int tx   = lane & 3;
    const int b    = blockIdx.x >> 5;
    const int n0t  = (blockIdx.x & 31) * 128;

    // ldmatrix lane geometry
    const int matq = lane >> 3, rowq = lane & 7;
    const int mrow  = (matq & 1) * 8 + rowq;
    const int acolw = (matq >> 1) * 4;
    const int nrow  = (matq >> 1) * 8 + rowq;
    const int bcolw = (matq & 1) * 4;

    if (tid < 128) s_ba[tid] = ba[tid];
    else if (tid < 192) s_b1[tid - 128] = b1[tid - 128];
    else if (tid < 256) s_b2[tid - 192] = b2[tid - 192];

    // ---- fill: X tile (128x256) split -> bf16 hi/lo; W2 split ----
    {
        const float4* X4 = (const float4*)(X + (size_t)(b * Nn + n0t) * Dd);
        #pragma unroll
        for (int it = 0; it < 8; it++) {
            int idx = tid + it * 512;            // 0..4095
            int row = idx >> 5, gg = idx & 31;
            float4 f0 = X4[row * 64 + gg * 2], f1 = X4[row * 64 + gg * 2 + 1];
            float v[8] = {f0.x, f0.y, f0.z, f0.w, f1.x, f1.y, f1.z, f1.w};
            uint4 H, L;
            pack8(v, H, L);
            *(uint4*)&smu[OFF_XH + row * 132 + gg * 4] = H;
            *(uint4*)&smu[OFF_XL + row * 132 + gg * 4] = L;
        }
        {
            int row = tid >> 3, gg = tid & 7;    // tid 0..511
            const float* src = W2 + (size_t)row * 64 + gg * 8;
            float v[8] = {src[0], src[1], src[2], src[3], src[4], src[5], src[6], src[7]};
            uint4 H, L;
            pack8(v, H, L);
            *(uint4*)&smu[OFF_W2_H + row * 36 + gg * 4] = H;
            *(uint4*)&smu[OFF_W2_L + row * 36 + gg * 4] = L;
        }
    }

    // ---- stage 1: Y[128 tok, 192] = X @ [Wa;W1]^T  (K=256 in 4 chunks) ----
    // warp grid 4x4: 32 tok x 48 cols per warp
    const int wm = (w & 3) * 32;
    const int wn = (w >> 2) * 48;
    float acc1[2][6][4];
    #pragma unroll
    for (int mt = 0; mt < 2; mt++)
        #pragma unroll
        for (int nb = 0; nb < 6; nb++)
            #pragma unroll
            for (int q = 0; q < 4; q++) acc1[mt][nb][q] = 0.0f;

    uint32_t aAh[2], aAl[2], aBh[3], aBl[3];
    #pragma unroll
    for (int mt = 0; mt < 2; mt++) {
        aAh[mt] = sptr(&smu[OFF_XH + (wm + mt * 16 + mrow) * 132 + acolw]);
        aAl[mt] = sptr(&smu[OFF_XL + (wm + mt * 16 + mrow) * 132 + acolw]);
    }
    #pragma unroll
    for (int pp = 0; pp < 3; pp++) {
        aBh[pp] = sptr(&smu[OFF_WC_H + (wn + pp * 16 + nrow) * 36 + bcolw]);
        aBl[pp] = sptr(&smu[OFF_WC_L + (wn + pp * 16 + nrow) * 36 + bcolw]);
    }

    for (int c = 0; c < 4; c++) {
        __syncthreads();
        #pragma unroll
        for (int it = 0; it < 3; it++) {
            int idx = tid + it * 512;            // 0..1535
            int row = idx >> 3, gg = idx & 7;
            const float* src = ((row < 128) ? (Wa + (size_t)row * Dd)
                                            : (W1 + (size_t)(row - 128) * Dd))
                               + c * 64 + gg * 8;
            float v[8] = {src[0], src[1], src[2], src[3], src[4], src[5], src[6], src[7]};
            uint4 H, L;
            pack8(v, H, L);
            *(uint4*)&smu[OFF_WC_H + row * 36 + gg * 4] = H;
            *(uint4*)&smu[OFF_WC_L + row * 36 + gg * 4] = L;
        }
        __syncthreads();

        #pragma unroll
        for (int s = 0; s < 4; s++) {
            const uint32_t offA = (uint32_t)(c * 32 + s * 8) * 4;
            const uint32_t offB = (uint32_t)(s * 8) * 4;
            uint32_t ah[2][4], al[2][4];
            LDSM4(ah[0][0], ah[0][1], ah[0][2], ah[0][3], aAh[0] + offA);
            LDSM4(ah[1][0], ah[1][1], ah[1][2], ah[1][3], aAh[1] + offA);
            LDSM4(al[0][0], al[0][1], al[0][2], al[0][3], aAl[0] + offA);
            LDSM4(al[1][0], al[1][1], al[1][2], al[1][3], aAl[1] + offA);
            #pragma unroll
            for (int pp = 0; pp < 3; pp++) {
                uint32_t bh[4], bl[4];
                LDSM4(bh[0], bh[1], bh[2], bh[3], aBh[pp] + offB);
                LDSM4(bl[0], bl[1], bl[2], bl[3], aBl[pp] + offB);
                #pragma unroll
                for (int e = 0; e < 2; e++) {
                    const int nb = pp * 2 + e;
                    #pragma unroll
                    for (int mt = 0; mt < 2; mt++) {
                        mma16(acc1[mt][nb], ah[mt], bh + e * 2);
                        mma16(acc1[mt][nb], ah[mt], bl + e * 2);
                        mma16(acc1[mt][nb], al[mt], bh + e * 2);
                    }
                }
            }
        }
    }
    __syncthreads();

    // ---- write Y column-major [col][tok] (fp32) ----
    #pragma unroll
    for (int mt = 0; mt < 2; mt++)
        #pragma unroll
        for (int nb = 0; nb < 6; nb++) {
            int row = wm + mt * 16 + ty;
            int col = wn + nb * 8 + 2 * tx;
            smf[OFF_Y + col * 132 + row]           = acc1[mt][nb][0];
            smf[OFF_Y + (col + 1) * 132 + row]     = acc1[mt][nb][1];
            smf[OFF_Y + col * 132 + row + 8]       = acc1[mt][nb][2];
            smf[OFF_Y + (col + 1) * 132 + row + 8] = acc1[mt][nb][3];
        }
    __syncthreads();

    // ---- softmax: 4 threads per token; then h-convert: 4 threads per token ----
    {
        const int tok = tid >> 2;
        const int j0 = (tid & 3) * 32;
        float mx = -1e30f;
        #pragma unroll 8
        for (int j = j0; j < j0 + 32; j++)
            mx = fmaxf(mx, smf[OFF_Y + j * 132 + tok] + s_ba[j]);
        mx = fmaxf(mx, __shfl_xor_sync(0xFFFFFFFFu, mx, 1));
        mx = fmaxf(mx, __shfl_xor_sync(0xFFFFFFFFu, mx, 2));
        float ssum = 0.0f;
        #pragma unroll 8
        for (int j = j0; j < j0 + 32; j++) {
            float e = __expf(smf[OFF_Y + j * 132 + tok] + s_ba[j] - mx);
            smf[OFF_Y + j * 132 + tok] = e;
            ssum += e;
        }
        ssum += __shfl_xor_sync(0xFFFFFFFFu, ssum, 1);
        ssum += __shfl_xor_sync(0xFFFFFFFFu, ssum, 2);
        const float inv = 1.0f / ssum;
        const int wrd = tok >> 1, hf = tok & 1;
        #pragma unroll 8
        for (int j = j0; j < j0 + 32; j++) {
            unsigned short hh, ll;
            split2(smf[OFF_Y + j * 132 + tok] * inv, hh, ll);
            st16s(smu, OFF_AT_H + j * 68 + wrd, hf, hh);
            st16s(smu, OFF_AT_L + j * 68 + wrd, hf, ll);
        }
        // h: this thread handles 16 e's of its token (2 groups of 8)
        #pragma unroll
        for (int g2 = 0; g2 < 2; g2++) {
            const int gg = (tid & 3) * 2 + g2;
            float v[8];
            #pragma unroll
            for (int q = 0; q < 8; q++) {
                int e = gg * 8 + q;
                float h = smf[OFF_Y + (128 + e) * 132 + tok] + s_b1[e];
                v[q] = (h >= 0.0f) ? h : 0.01f * h;
            }
            uint4 H, L;
            pack8(v, H, L);
            *(uint4*)&smu[OFF_H_H + tok * 36 + gg * 4] = H;
            *(uint4*)&smu[OFF_H_L + tok * 36 + gg * 4] = L;
        }
    }
    __syncthreads();

    // ---- stage 2: sq[128 tok, 64] = h @ W2^T (K=64); 16 tok x 32 f per warp ----
    const int m2 = (w & 7) * 16;
    const int nsel = w >> 3;            // 0 or 1
    float acc2[4][4];
    #pragma unroll
    for (int nb = 0; nb < 4; nb++)
        #pragma unroll
        for (int q = 0; q < 4; q++) acc2[nb][q] = 0.0f;

    {
        const uint32_t aH2h = sptr(&smu[OFF_H_H + (m2 + mrow) * 36 + acolw]);
        const uint32_t aH2l = sptr(&smu[OFF_H_L + (m2 + mrow) * 36 + acolw]);
        uint32_t aW2h[2], aW2l[2];
        #pragma unroll
        for (int pl = 0; pl < 2; pl++) {
            aW2h[pl] = sptr(&smu[OFF_W2_H + ((nsel * 2 + pl) * 16 + nrow) * 36 + bcolw]);
            aW2l[pl] = sptr(&smu[OFF_W2_L + ((nsel * 2 + pl) * 16 + nrow) * 36 + bcolw]);
        }
        #pragma unroll
        for (int s = 0; s < 4; s++) {
            const uint32_t off = (uint32_t)(s * 8) * 4;
            uint32_t ah[4], al[4];
            LDSM4(ah[0], ah[1], ah[2], ah[3], aH2h + off);
            LDSM4(al[0], al[1], al[2], al[3], aH2l + off);
            #pragma unroll
            for (int pl = 0; pl < 2; pl++) {
                uint32_t bh[4], bl[4];
                LDSM4(bh[0], bh[1], bh[2], bh[3], aW2h[pl] + off);
                LDSM4(bl[0], bl[1], bl[2], bl[3], aW2l[pl] + off);
                #pragma unroll
                for (int e = 0; e < 2; e++) {
                    const int nb = pl * 2 + e;
                    mma16(acc2[nb], ah, bh + e * 2);
                    mma16(acc2[nb], ah, bl + e * 2);
                    mma16(acc2[nb], al, bh + e * 2);
                }
            }
        }
    }
    __syncthreads();   // all stage-2 reads of h done before sq^T overwrites it

    // ---- write sq^T [d][tok] (+b2) as bf16 hi/lo; append ones row (d=64) ----
    #pragma unroll
    for (int nb = 0; nb < 4; nb++)
        #pragma unroll
        for (int q = 0; q < 4; q++) {
            int row = m2 + ty + ((q >> 1) << 3);             // token
            int col = nsel * 32 + nb * 8 + 2 * tx + (q & 1); // d
            unsigned short hh, ll;
            split2(acc2[nb][q] + s_b2[col], hh, ll);
            st16s(smu, OFF_SQ_H + col * 68 + (row >> 1), row & 1, hh);
            st16s(smu, OFF_SQ_L + col * 68 + (row >> 1), row & 1, ll);
        }
    if (tid < 128) {
        const int tok = tid, wrd = tok >> 1, hf = tok & 1;
        st16s(smu, OFF_SQ_H + 64 * 68 + wrd, hf, (unsigned short)0x3F80);
        st16s(smu, OFF_SQ_L + 64 * 68 + wrd, hf, 0);
        #pragma unroll
        for (int rr = 65; rr < 72; rr++) {
            st16s(smu, OFF_SQ_H + rr * 68 + wrd, hf, 0);
            st16s(smu, OFF_SQ_L + rr * 68 + wrd, hf, 0);
        }
    }
    __syncthreads();

    // ---- stage 3: D3[128 cl, 72] = assign^T @ [sq | 1]  (K=128 tokens) ----
    // 16 cl x 32 d per warp; upper warps (nsel=1) also do the ones-block (mass)
    float acc3[4][4];
    float acc3m[4];
    #pragma unroll
    for (int nb = 0; nb < 4; nb++)
        #pragma unroll
        for (int q = 0; q < 4; q++) acc3[nb][q] = 0.0f;
    #pragma unroll
    for (int q = 0; q < 4; q++) acc3m[q] = 0.0f;

    {
        const uint32_t aA3h = sptr(&smu[OFF_AT_H + (m2 + mrow) * 68 + acolw]);
        const uint32_t aA3l = sptr(&smu[OFF_AT_L + (m2 + mrow) * 68 + acolw]);
        uint32_t aB3h[2], aB3l[2];
        #pragma unroll
        for (int pl = 0; pl < 2; pl++) {
            aB3h[pl] = sptr(&smu[OFF_SQ_H + ((nsel * 2 + pl) * 16 + nrow) * 68 + bcolw]);
            aB3l[pl] = sptr(&smu[OFF_SQ_L + ((nsel * 2 + pl) * 16 + nrow) * 68 + bcolw]);
        }
        const int mat2 = (lane >> 3) & 1;
        const uint32_t aB9h = sptr(&smu[OFF_SQ_H + (64 + rowq) * 68 + mat2 * 4]);
        const uint32_t aB9l = sptr(&smu[OFF_SQ_L + (64 + rowq) * 68 + mat2 * 4]);

        #pragma unroll
        for (int s = 0; s < 8; s++) {
            const uint32_t off = (uint32_t)(s * 8) * 4;
            uint32_t ah[4], al[4];
            LDSM4(ah[0], ah[1], ah[2], ah[3], aA3h + off);
            LDSM4(al[0], al[1], al[2], al[3], aA3l + off);
            #pragma unroll
            for (int pl = 0; pl < 2; pl++) {
                uint32_t bh[4], bl[4];
                LDSM4(bh[0], bh[1], bh[2], bh[3], aB3h[pl] + off);
                LDSM4(bl[0], bl[1], bl[2], bl[3], aB3l[pl] + off);
                #pragma unroll
                for (int e = 0; e < 2; e++) {
                    const int nb = pl * 2 + e;
                    mma16(acc3[nb], ah, bh + e * 2);
                    mma16(acc3[nb], ah, bl + e * 2);
                    mma16(acc3[nb], al, bh + e * 2);
                }
            }
            if (nsel) {
                uint32_t b9h[2], b9l[2];
                LDSM2(b9h[0], b9h[1], aB9h + off);
                LDSM2(b9l[0], b9l[1], aB9l + off);
                mma16(acc3m, ah, b9h);
                mma16(acc3m, ah, b9l);
                mma16(acc3m, al, b9h);
            }
        }
    }

    // ---- epilogue: atomics ----
    {
        const size_t base0 = ((size_t)b * Kk + m2 + ty) * Dc;
        #pragma unroll
        for (int nb = 0; nb < 4; nb++) {
            int d0 = nsel * 32 + nb * 8 + 2 * tx;
            atomicAdd(&g_agg[base0 + d0],              acc3[nb][0]);
            atomicAdd(&g_agg[base0 + d0 + 1],          acc3[nb][1]);
            atomicAdd(&g_agg[base0 + 8 * Dc + d0],     acc3[nb][2]);
            atomicAdd(&g_agg[base0 + 8 * Dc + d0 + 1], acc3[nb][3]);
        }
        if (nsel && tx == 0) {
            atomicAdd(&g_mass[b * Kk + m2 + ty],     acc3m[0]);
            atomicAdd(&g_mass[b * Kk + m2 + ty + 8], acc3m[2]);
        }
    }
}

// ---------------- finalize, pass 1: vlad + partial sum-of-squares ----------------
__global__ void __launch_bounds__(256) k_vlad(const float* __restrict__ centroid,
                                              float* __restrict__ out) {
    const int b = blockIdx.x;
    const int seg = blockIdx.y;
    const int i = seg * 1024 + threadIdx.x * 4;
    const size_t gi = (size_t)b * (Kk * Dc) + i;
    const int k = i >> 6;
    const float m = g_mass[b * Kk + k];
    float4 a = *(const float4*)&g_agg[gi];
    float4 c = *(const float4*)&centroid[i];
    float4 v;
    v.x = a.x - m * c.x;
    v.y = a.y - m * c.y;
    v.z = a.z - m * c.z;
    v.w = a.w - m * c.w;
    *(float4*)&out[gi] = v;
    float ss = v.x * v.x + v.y * v.y + v.z * v.z + v.w * v.w;
    #pragma unroll
    for (int d = 16; d > 0; d >>= 1) ss += __shfl_xor_sync(0xFFFFFFFFu, ss, d);
    if ((threadIdx.x & 31) == 0) atomicAdd(&g_ss[b], ss);
}

// ---------------- finalize, pass 2: scale by 1/max(norm, eps) ----------------
__global__ void __launch_bounds__(256) k_scale(float* __restrict__ out) {
    const int b = blockIdx.x;
    const float n = sqrtf(g_ss[b]);
    const float inv = 1.0f / fmaxf(n, 1e-12f);
    const int i = blockIdx.y * 1024 + threadIdx.x * 4;
    const size_t gi = (size_t)b * (Kk * Dc) + i;
    float4 v = *(float4*)&out[gi];
    v.x *= inv; v.y *= inv; v.z *= inv; v.w *= inv;
    *(float4*)&out[gi] = v;
}

// ---------------- launch ----------------
extern "C" void kernel_launch(void* const* d_in, const int* in_sizes, int n_in,
                              void* d_out, int out_size) {
    const float* X        = (const float*)d_in[0];
    const float* W1       = (const float*)d_in[1];
    const float* b1       = (const float*)d_in[2];
    const float* W2       = (const float*)d_in[3];
    const float* b2       = (const float*)d_in[4];
    const float* Wa       = (const float*)d_in[5];
    const float* ba       = (const float*)d_in[6];
    const float* centroid = (const float*)d_in[7];
    float* out = (float*)d_out;

    cudaFuncSetAttribute(k_fused, cudaFuncAttributeMaxDynamicSharedMemorySize,
                         SMEM_WORDS * 4);

    k_init<<<1041, 256>>>();
    k_fused<<<1024, 512, SMEM_WORDS * 4>>>(X, W1, b1, W2, b2, Wa, ba);
    dim3 gn(Bb, 8);
    k_vlad<<<gn, 256>>>(centroid, out);
    k_scale<<<gn, 256>>>(out);
}

// round 14
// speedup vs baseline: 1.1767x; 1.1767x over previous
#include <cuda_runtime.h>
#include <cuda_bf16.h>
#include <math.h>
#include <stdint.h>

#define Bb 32
#define Nn 4096
#define Dd 256
#define Kk 128
#define Dc 64

// ---------------- device scratch ----------------
__device__ float g_agg[(size_t)Bb * Kk * Dc];
__device__ float g_mass[Bb * Kk];
__device__ float g_ss[Bb];
// pre-split weights, bf16 hi/lo packed 2-per-word, chunked to match smem layout
__device__ __align__(16) uint32_t g_WcH[4 * 192 * 32], g_WcL[4 * 192 * 32];
__device__ __align__(16) uint32_t g_W2H[64 * 32],      g_W2L[64 * 32];

// ---------------- smem word-offset layout (32-bit words) ----------------
#define OFF_XH   0        // X hi  [128 tok][132]
#define OFF_XL   16896
#define OFF_WC_H 33792    // W chunk hi [192 row][36]
#define OFF_WC_L 40704
#define OFF_Y    0        // Y fp32 col-major [192 col][132 tok]
#define OFF_AT_H 25344    // assign^T hi [128 cl][68]
#define OFF_AT_L 34048
#define OFF_H_H  42752    // h hi [128 tok][36]
#define OFF_H_L  47360
#define OFF_SQ_H 42752    // sq^T hi [72 d][68] (aliases h after stage 2)
#define OFF_SQ_L 47648
#define OFF_W2_H 52544    // W2 hi [64 f][36]
#define OFF_W2_L 54848
#define SMEM_WORDS 57152  // 228608 bytes

// ---------------- helpers ----------------
__device__ __forceinline__ void split2(float x, unsigned short& h, unsigned short& l) {
    __nv_bfloat16 hb = __float2bfloat16_rn(x);
    float lf = x - __bfloat162float(hb);
    h = __bfloat16_as_ushort(hb);
    l = __bfloat16_as_ushort(__float2bfloat16_rn(lf));
}
__device__ __forceinline__ uint32_t bf162_bits(__nv_bfloat162 v) {
    return *reinterpret_cast<uint32_t*>(&v);
}
// fast pairwise split: 1 bf16x2 cvt (hi), shift/mask reconstruct, 1 bf16x2 cvt (lo)
__device__ __forceinline__ void pack8(const float* v, uint4& H, uint4& L) {
    uint32_t* Hp = &H.x;
    uint32_t* Lp = &L.x;
    #pragma unroll
    for (int p = 0; p < 4; p++) {
        float v0 = v[2 * p], v1 = v[2 * p + 1];
        uint32_t hw = bf162_bits(__float22bfloat162_rn(make_float2(v0, v1)));
        float h0 = __uint_as_float(hw << 16);
        float h1 = __uint_as_float(hw & 0xFFFF0000u);
        uint32_t lw = bf162_bits(__float22bfloat162_rn(make_float2(v0 - h0, v1 - h1)));
        Hp[p] = hw;
        Lp[p] = lw;
    }
}
__device__ __forceinline__ void mma16(float* d, const uint32_t* a, const uint32_t* b) {
    asm volatile(
        "mma.sync.aligned.m16n8k16.row.col.f32.bf16.bf16.f32 "
        "{%0,%1,%2,%3}, {%4,%5,%6,%7}, {%8,%9}, {%0,%1,%2,%3};"
        : "+f"(d[0]), "+f"(d[1]), "+f"(d[2]), "+f"(d[3])
        : "r"(a[0]), "r"(a[1]), "r"(a[2]), "r"(a[3]), "r"(b[0]), "r"(b[1]));
}
__device__ __forceinline__ void st16s(uint32_t* smu, int word, int half, unsigned short v) {
    ((unsigned short*)&smu[word])[half] = v;
}
__device__ __forceinline__ uint32_t sptr(const void* p) {
    return (uint32_t)__cvta_generic_to_shared(p);
}
#define LDSM4(R0, R1, R2, R3, A) \
    asm volatile("ldmatrix.sync.aligned.m8n8.x4.shared.b16 {%0,%1,%2,%3}, [%4];" \
                 : "=r"(R0), "=r"(R1), "=r"(R2), "=r"(R3) : "r"(A))
#define LDSM2(R0, R1, A) \
    asm volatile("ldmatrix.sync.aligned.m8n8.x2.shared.b16 {%0,%1}, [%2];" \
                 : "=r"(R0), "=r"(R1) : "r"(A))
#define CP16(dst, src) \
    asm volatile("cp.async.cg.shared.global [%0], [%1], 16;" :: "r"(dst), "l"(src))
#define CP_COMMIT() asm volatile("cp.async.commit_group;" ::: "memory")
#define CP_WAIT0()  asm volatile("cp.async.wait_group 0;" ::: "memory")

// ---------------- prep: split weights once into chunked bf16 hi/lo ----------------
__global__ void __launch_bounds__(256) k_prep(const float* __restrict__ W1,
                                              const float* __restrict__ W2,
                                              const float* __restrict__ Wa) {
    int i = blockIdx.x * 256 + threadIdx.x;
    if (i < 24576) {                      // [Wa;W1]: 4 chunks x 192 rows x 32 words
        int c = i / 6144, rem = i % 6144;
        int r = rem >> 5, ww = rem & 31;
        const float* src = (r < 128) ? (Wa + (size_t)r * Dd) : (W1 + (size_t)(r - 128) * Dd);
        float f0 = src[c * 64 + 2 * ww], f1 = src[c * 64 + 2 * ww + 1];
        unsigned short h0, l0, h1, l1;
        split2(f0, h0, l0);
        split2(f1, h1, l1);
        g_WcH[i] = (uint32_t)h0 | ((uint32_t)h1 << 16);
        g_WcL[i] = (uint32_t)l0 | ((uint32_t)l1 << 16);
    } else if (i < 24576 + 2048) {        // W2: 64 rows x 32 words
        int j = i - 24576;
        int r = j >> 5, ww = j & 31;
        float f0 = W2[(size_t)r * 64 + 2 * ww], f1 = W2[(size_t)r * 64 + 2 * ww + 1];
        unsigned short h0, l0, h1, l1;
        split2(f0, h0, l0);
        split2(f1, h1, l1);
        g_W2H[j] = (uint32_t)h0 | ((uint32_t)h1 << 16);
        g_W2L[j] = (uint32_t)l0 | ((uint32_t)l1 << 16);
    }
}

// ---------------- init ----------------
__global__ void __launch_bounds__(256) k_init() {
    int i = blockIdx.x * 256 + threadIdx.x;
    if (i < Bb * Kk * Dc) g_agg[i] = 0.0f;
    else if (i < Bb * Kk * Dc + Bb * Kk) g_mass[i - Bb * Kk * Dc] = 0.0f;
    else if (i < Bb * Kk * Dc + Bb * Kk + Bb) g_ss[i - Bb * Kk * Dc - Bb * Kk] = 0.0f;
}

// ---------------- fused main kernel: one 128-token tile per block, 512 threads ----------------
__global__ void __launch_bounds__(512, 1) k_fused(
    const float* __restrict__ X,  const float* __restrict__ b1,
    const float* __restrict__ b2, const float* __restrict__ ba)
{
    extern __shared__ float smf[];
    uint32_t* smu = (uint32_t*)smf;
    __shared__ float s_ba[128], s_b1[64], s_b2[64];

    const int tid  = threadIdx.x;
    const int w    = tid >> 5;          // 0..15
    const int lane = tid & 31;
    const int ty   = lane >> 2;
    const int tx   = lane & 3;
    const int b    = blockIdx.x >> 5;
    const int n0t  = (blockIdx.x & 31) * 128;

    // ldmatrix lane geometry
    const int matq = lane >> 3, rowq = lane & 7;
    const int mrow  = (matq & 1) * 8 + rowq;
    const int acolw = (matq >> 1) * 4;
    const int nrow  = (matq >> 1) * 8 + rowq;
    const int bcolw = (matq & 1) * 4;

    // ---- prologue: issue async copies for W2 + W chunk 0, then do X fill ----
    {
        int row = tid >> 3, seg = tid & 7;    // tid 0..511 -> 64 rows x 8 segs
        CP16(sptr(&smu[OFF_W2_H + row * 36 + seg * 4]), &g_W2H[row * 32 + seg * 4]);
        CP16(sptr(&smu[OFF_W2_L + row * 36 + seg * 4]), &g_W2L[row * 32 + seg * 4]);
    }
    #pragma unroll
    for (int it = 0; it < 3; it++) {
        int idx = tid + it * 512;            // 0..1535 -> 192 rows x 8 segs
        int row = idx >> 3, seg = idx & 7;
        CP16(sptr(&smu[OFF_WC_H + row * 36 + seg * 4]), &g_WcH[row * 32 + seg * 4]);
        CP16(sptr(&smu[OFF_WC_L + row * 36 + seg * 4]), &g_WcL[row * 32 + seg * 4]);
    }
    CP_COMMIT();

    if (tid < 128) s_ba[tid] = ba[tid];
    else if (tid < 192) s_b1[tid - 128] = b1[tid - 128];
    else if (tid < 256) s_b2[tid - 192] = b2[tid - 192];

    // ---- X tile (128x256) split -> bf16 hi/lo (overlaps cp.async loads) ----
    {
        const float4* X4 = (const float4*)(X + (size_t)(b * Nn + n0t) * Dd);
        #pragma unroll
        for (int it = 0; it < 8; it++) {
            int idx = tid + it * 512;            // 0..4095
            int row = idx >> 5, gg = idx & 31;
            float4 f0 = X4[row * 64 + gg * 2], f1 = X4[row * 64 + gg * 2 + 1];
            float v[8] = {f0.x, f0.y, f0.z, f0.w, f1.x, f1.y, f1.z, f1.w};
            uint4 H, L;
            pack8(v, H, L);
            *(uint4*)&smu[OFF_XH + row * 132 + gg * 4] = H;
            *(uint4*)&smu[OFF_XL + row * 132 + gg * 4] = L;
        }
    }

    // ---- stage 1: Y[128 tok, 192] = X @ [Wa;W1]^T  (K=256 in 4 chunks) ----
    const int wm = (w & 3) * 32;
    const int wn = (w >> 2) * 48;
    float acc1[2][6][4];
    #pragma unroll
    for (int mt = 0; mt < 2; mt++)
        #pragma unroll
        for (int nb = 0; nb < 6; nb++)
            #pragma unroll
            for (int q = 0; q < 4; q++) acc1[mt][nb][q] = 0.0f;

    uint32_t aAh[2], aAl[2], aBh[3], aBl[3];
    #pragma unroll
    for (int mt = 0; mt < 2; mt++) {
        aAh[mt] = sptr(&smu[OFF_XH + (wm + mt * 16 + mrow) * 132 + acolw]);
        aAl[mt] = sptr(&smu[OFF_XL + (wm + mt * 16 + mrow) * 132 + acolw]);
    }
    #pragma unroll
    for (int pp = 0; pp < 3; pp++) {
        aBh[pp] = sptr(&smu[OFF_WC_H + (wn + pp * 16 + nrow) * 36 + bcolw]);
        aBl[pp] = sptr(&smu[OFF_WC_L + (wn + pp * 16 + nrow) * 36 + bcolw]);
    }

    for (int c = 0; c < 4; c++) {
        if (c > 0) {
            __syncthreads();   // previous chunk's compute done before overwrite
            #pragma unroll
            for (int it = 0; it < 3; it++) {
                int idx = tid + it * 512;
                int row = idx >> 3, seg = idx & 7;
                CP16(sptr(&smu[OFF_WC_H + row * 36 + seg * 4]),
                     &g_WcH[c * 6144 + row * 32 + seg * 4]);
                CP16(sptr(&smu[OFF_WC_L + row * 36 + seg * 4]),
                     &g_WcL[c * 6144 + row * 32 + seg * 4]);
            }
            CP_COMMIT();
        }
        CP_WAIT0();
        __syncthreads();

        #pragma unroll
        for (int s = 0; s < 4; s++) {
            const uint32_t offA = (uint32_t)(c * 32 + s * 8) * 4;
            const uint32_t offB = (uint32_t)(s * 8) * 4;
            uint32_t ah[2][4], al[2][4];
            LDSM4(ah[0][0], ah[0][1], ah[0][2], ah[0][3], aAh[0] + offA);
            LDSM4(ah[1][0], ah[1][1], ah[1][2], ah[1][3], aAh[1] + offA);
            LDSM4(al[0][0], al[0][1], al[0][2], al[0][3], aAl[0] + offA);
            LDSM4(al[1][0], al[1][1], al[1][2], al[1][3], aAl[1] + offA);
            #pragma unroll
            for (int pp = 0; pp < 3; pp++) {
                uint32_t bh[4], bl[4];
                LDSM4(bh[0], bh[1], bh[2], bh[3], aBh[pp] + offB);
                LDSM4(bl[0], bl[1], bl[2], bl[3], aBl[pp] + offB);
                #pragma unroll
                for (int e = 0; e < 2; e++) {
                    const int nb = pp * 2 + e;
                    #pragma unroll
                    for (int mt = 0; mt < 2; mt++) {
                        mma16(acc1[mt][nb], ah[mt], bh + e * 2);
                        mma16(acc1[mt][nb], ah[mt], bl + e * 2);
                        mma16(acc1[mt][nb], al[mt], bh + e * 2);
                    }
                }
            }
        }
    }
    __syncthreads();

    // ---- write Y column-major [col][tok] (fp32) ----
    #pragma unroll
    for (int mt = 0; mt < 2; mt++)
        #pragma unroll
        for (int nb = 0; nb < 6; nb++) {
            int row = wm + mt * 16 + ty;
            int col = wn + nb * 8 + 2 * tx;
            smf[OFF_Y + col * 132 + row]           = acc1[mt][nb][0];
            smf[OFF_Y + (col + 1) * 132 + row]     = acc1[mt][nb][1];
            smf[OFF_Y + col * 132 + row + 8]       = acc1[mt][nb][2];
            smf[OFF_Y + (col + 1) * 132 + row + 8] = acc1[mt][nb][3];
        }
    __syncthreads();

    // ---- softmax: 4 threads per token; then h-convert: 4 threads per token ----
    {
        const int tok = tid >> 2;
        const int j0 = (tid & 3) * 32;
        float mx = -1e30f;
        #pragma unroll 8
        for (int j = j0; j < j0 + 32; j++)
            mx = fmaxf(mx, smf[OFF_Y + j * 132 + tok] + s_ba[j]);
        mx = fmaxf(mx, __shfl_xor_sync(0xFFFFFFFFu, mx, 1));
        mx = fmaxf(mx, __shfl_xor_sync(0xFFFFFFFFu, mx, 2));
        float ssum = 0.0f;
        #pragma unroll 8
        for (int j = j0; j < j0 + 32; j++) {
            float e = __expf(smf[OFF_Y + j * 132 + tok] + s_ba[j] - mx);
            smf[OFF_Y + j * 132 + tok] = e;
            ssum += e;
        }
        ssum += __shfl_xor_sync(0xFFFFFFFFu, ssum, 1);
        ssum += __shfl_xor_sync(0xFFFFFFFFu, ssum, 2);
        const float inv = 1.0f / ssum;
        const int wrd = tok >> 1, hf = tok & 1;
        #pragma unroll 8
        for (int j = j0; j < j0 + 32; j++) {
            unsigned short hh, ll;
            split2(smf[OFF_Y + j * 132 + tok] * inv, hh, ll);
            st16s(smu, OFF_AT_H + j * 68 + wrd, hf, hh);
            st16s(smu, OFF_AT_L + j * 68 + wrd, hf, ll);
        }
        // h: this thread handles 16 e's of its token (2 groups of 8)
        #pragma unroll
        for (int g2 = 0; g2 < 2; g2++) {
            const int gg = (tid & 3) * 2 + g2;
            float v[8];
            #pragma unroll
            for (int q = 0; q < 8; q++) {
                int e = gg * 8 + q;
                float h = smf[OFF_Y + (128 + e) * 132 + tok] + s_b1[e];
                v[q] = (h >= 0.0f) ? h : 0.01f * h;
            }
            uint4 H, L;
            pack8(v, H, L);
            *(uint4*)&smu[OFF_H_H + tok * 36 + gg * 4] = H;
            *(uint4*)&smu[OFF_H_L + tok * 36 + gg * 4] = L;
        }
    }
    __syncthreads();

    // ---- stage 2: sq[128 tok, 64] = h @ W2^T (K=64); 16 tok x 32 f per warp ----
    const int m2 = (w & 7) * 16;
    const int nsel = w >> 3;            // 0 or 1
    float acc2[4][4];
    #pragma unroll
    for (int nb = 0; nb < 4; nb++)
        #pragma unroll
        for (int q = 0; q < 4; q++) acc2[nb][q] = 0.0f;

    {
        const uint32_t aH2h = sptr(&smu[OFF_H_H + (m2 + mrow) * 36 + acolw]);
        const uint32_t aH2l = sptr(&smu[OFF_H_L + (m2 + mrow) * 36 + acolw]);
        uint32_t aW2h[2], aW2l[2];
        #pragma unroll
        for (int pl = 0; pl < 2; pl++) {
            aW2h[pl] = sptr(&smu[OFF_W2_H + ((nsel * 2 + pl) * 16 + nrow) * 36 + bcolw]);
            aW2l[pl] = sptr(&smu[OFF_W2_L + ((nsel * 2 + pl) * 16 + nrow) * 36 + bcolw]);
        }
        #pragma unroll
        for (int s = 0; s < 4; s++) {
            const uint32_t off = (uint32_t)(s * 8) * 4;
            uint32_t ah[4], al[4];
            LDSM4(ah[0], ah[1], ah[2], ah[3], aH2h + off);
            LDSM4(al[0], al[1], al[2], al[3], aH2l + off);
            #pragma unroll
            for (int pl = 0; pl < 2; pl++) {
                uint32_t bh[4], bl[4];
                LDSM4(bh[0], bh[1], bh[2], bh[3], aW2h[pl] + off);
                LDSM4(bl[0], bl[1], bl[2], bl[3], aW2l[pl] + off);
                #pragma unroll
                for (int e = 0; e < 2; e++) {
                    const int nb = pl * 2 + e;
                    mma16(acc2[nb], ah, bh + e * 2);
                    mma16(acc2[nb], ah, bl + e * 2);
                    mma16(acc2[nb], al, bh + e * 2);
                }
            }
        }
    }
    __syncthreads();   // all stage-2 reads of h done before sq^T overwrites it

    // ---- write sq^T [d][tok] (+b2) as bf16 hi/lo; append ones row (d=64) ----
    #pragma unroll
    for (int nb = 0; nb < 4; nb++)
        #pragma unroll
        for (int q = 0; q < 4; q++) {
            int row = m2 + ty + ((q >> 1) << 3);             // token
            int col = nsel * 32 + nb * 8 + 2 * tx + (q & 1); // d
            unsigned short hh, ll;
            split2(acc2[nb][q] + s_b2[col], hh, ll);
            st16s(smu, OFF_SQ_H + col * 68 + (row >> 1), row & 1, hh);
            st16s(smu, OFF_SQ_L + col * 68 + (row >> 1), row & 1, ll);
        }
    if (tid < 128) {
        const int tok = tid, wrd = tok >> 1, hf = tok & 1;
        st16s(smu, OFF_SQ_H + 64 * 68 + wrd, hf, (unsigned short)0x3F80);
        st16s(smu, OFF_SQ_L + 64 * 68 + wrd, hf, 0);
        #pragma unroll
        for (int rr = 65; rr < 72; rr++) {
            st16s(smu, OFF_SQ_H + rr * 68 + wrd, hf, 0);
            st16s(smu, OFF_SQ_L + rr * 68 + wrd, hf, 0);
        }
    }
    __syncthreads();

    // ---- stage 3: D3[128 cl, 72] = assign^T @ [sq | 1]  (K=128 tokens) ----
    float acc3[4][4];
    float acc3m[4];
    #pragma unroll
    for (int nb = 0; nb < 4; nb++)
        #pragma unroll
        for (int q = 0; q < 4; q++) acc3[nb][q] = 0.0f;
    #pragma unroll
    for (int q = 0; q < 4; q++) acc3m[q] = 0.0f;

    {
        const uint32_t aA3h = sptr(&smu[OFF_AT_H + (m2 + mrow) * 68 + acolw]);
        const uint32_t aA3l = sptr(&smu[OFF_AT_L + (m2 + mrow) * 68 + acolw]);
        uint32_t aB3h[2], aB3l[2];
        #pragma unroll
        for (int pl = 0; pl < 2; pl++) {
            aB3h[pl] = sptr(&smu[OFF_SQ_H + ((nsel * 2 + pl) * 16 + nrow) * 68 + bcolw]);
            aB3l[pl] = sptr(&smu[OFF_SQ_L + ((nsel * 2 + pl) * 16 + nrow) * 68 + bcolw]);
        }
        const int mat2 = (lane >> 3) & 1;
        const uint32_t aB9h = sptr(&smu[OFF_SQ_H + (64 + rowq) * 68 + mat2 * 4]);
        const uint32_t aB9l = sptr(&smu[OFF_SQ_L + (64 + rowq) * 68 + mat2 * 4]);

        #pragma unroll
        for (int s = 0; s < 8; s++) {
            const uint32_t off = (uint32_t)(s * 8) * 4;
            uint32_t ah[4], al[4];
            LDSM4(ah[0], ah[1], ah[2], ah[3], aA3h + off);
            LDSM4(al[0], al[1], al[2], al[3], aA3l + off);
            #pragma unroll
            for (int pl = 0; pl < 2; pl++) {
                uint32_t bh[4], bl[4];
                LDSM4(bh[0], bh[1], bh[2], bh[3], aB3h[pl] + off);
                LDSM4(bl[0], bl[1], bl[2], bl[3], aB3l[pl] + off);
                #pragma unroll
                for (int e = 0; e < 2; e++) {
                    const int nb = pl * 2 + e;
                    mma16(acc3[nb], ah, bh + e * 2);
                    mma16(acc3[nb], ah, bl + e * 2);
                    mma16(acc3[nb], al, bh + e * 2);
                }
            }
            if (nsel) {
                uint32_t b9h[2], b9l[2];
                LDSM2(b9h[0], b9h[1], aB9h + off);
                LDSM2(b9l[0], b9l[1], aB9l + off);
                mma16(acc3m, ah, b9h);
                mma16(acc3m, ah, b9l);
                mma16(acc3m, al, b9h);
            }
        }
    }

    // ---- epilogue: atomics ----
    {
        const size_t base0 = ((size_t)b * Kk + m2 + ty) * Dc;
        #pragma unroll
        for (int nb = 0; nb < 4; nb++) {
            int d0 = nsel * 32 + nb * 8 + 2 * tx;
            atomicAdd(&g_agg[base0 + d0],              acc3[nb][0]);
            atomicAdd(&g_agg[base0 + d0 + 1],          acc3[nb][1]);
            atomicAdd(&g_agg[base0 + 8 * Dc + d0],     acc3[nb][2]);
            atomicAdd(&g_agg[base0 + 8 * Dc + d0 + 1], acc3[nb][3]);
        }
        if (nsel && tx == 0) {
            atomicAdd(&g_mass[b * Kk + m2 + ty],     acc3m[0]);
            atomicAdd(&g_mass[b * Kk + m2 + ty + 8], acc3m[2]);
        }
    }
}

// ---------------- finalize, pass 1: vlad + partial sum-of-squares ----------------
__global__ void __launch_bounds__(256) k_vlad(const float* __restrict__ centroid,
                                              float* __restrict__ out) {
    const int b = blockIdx.x;
    const int seg = blockIdx.y;
    const int i = seg * 1024 + threadIdx.x * 4;
    const size_t gi = (size_t)b * (Kk * Dc) + i;
    const int k = i >> 6;
    const float m = g_mass[b * Kk + k];
    float4 a = *(const float4*)&g_agg[gi];
    float4 c = *(const float4*)&centroid[i];
    float4 v;
    v.x = a.x - m * c.x;
    v.y = a.y - m * c.y;
    v.z = a.z - m * c.z;
    v.w = a.w - m * c.w;
    *(float4*)&out[gi] = v;
    float ss = v.x * v.x + v.y * v.y + v.z * v.z + v.w * v.w;
    #pragma unroll
    for (int d = 16; d > 0; d >>= 1) ss += __shfl_xor_sync(0xFFFFFFFFu, ss, d);
    if ((threadIdx.x & 31) == 0) atomicAdd(&g_ss[b], ss);
}

// ---------------- finalize, pass 2: scale by 1/max(norm, eps) ----------------
__global__ void __launch_bounds__(256) k_scale(float* __restrict__ out) {
    const int b = blockIdx.x;
    const float n = sqrtf(g_ss[b]);
    const float inv = 1.0f / fmaxf(n, 1e-12f);
    const int i = blockIdx.y * 1024 + threadIdx.x * 4;
    const size_t gi = (size_t)b * (Kk * Dc) + i;
    float4 v = *(float4*)&out[gi];
    v.x *= inv; v.y *= inv; v.z *= inv; v.w *= inv;
    *(float4*)&out[gi] = v;
}

// ---------------- launch ----------------
extern "C" void kernel_launch(void* const* d_in, const int* in_sizes, int n_in,
                              void* d_out, int out_size) {
    const float* X        = (const float*)d_in[0];
    const float* W1       = (const float*)d_in[1];
    const float* b1       = (const float*)d_in[2];
    const float* W2       = (const float*)d_in[3];
    const float* b2       = (const float*)d_in[4];
    const float* Wa       = (const float*)d_in[5];
    const float* ba       = (const float*)d_in[6];
    const float* centroid = (const float*)d_in[7];
    float* out = (float*)d_out;

    cudaFuncSetAttribute(k_fused, cudaFuncAttributeMaxDynamicSharedMemorySize,
                         SMEM_WORDS * 4);

    k_prep<<<104, 256>>>(W1, W2, Wa);
    k_init<<<1041, 256>>>();
    k_fused<<<1024, 512, SMEM_WORDS * 4>>>(X, b1, b2, ba);
    dim3 gn(Bb, 8);
    k_vlad<<<gn, 256>>>(centroid, out);
    k_scale<<<gn, 256>>>(out);
}

// round 15
// speedup vs baseline: 1.3803x; 1.1730x over previous
#include <cuda_runtime.h>
#include <cuda_fp16.h>
#include <math.h>
#include <stdint.h>

#define Bb 32
#define Nn 4096
#define Dd 256
#define Kk 128
#define Dc 64

// ---------------- device scratch ----------------
__device__ float g_agg[(size_t)Bb * Kk * Dc];
__device__ float g_mass[Bb * Kk];
__device__ float g_ss[Bb];
// pre-split weights, fp16 hi packed 2-per-word, chunked to match smem layout
__device__ __align__(16) uint32_t g_WcH[4 * 192 * 32];
__device__ __align__(16) uint32_t g_W2H[64 * 32];

// ---------------- smem word-offset layout (32-bit words) ----------------
#define OFF_XH   0        // X hi  [128 tok][132]
#define OFF_XL   16896    //      -> 33792
#define OFF_WC_H 33792    // W chunk hi [192 row][36] -> 40704
#define OFF_Y    0        // Y fp32 col-major [192 col][132 tok] -> 25344
#define OFF_AT_H 25344    // assign^T hi [128 cl][68] -> 34048
#define OFF_AT_L 34048    //             -> 42752
#define OFF_H_H  42752    // h hi [128 tok][36] -> 47360
#define OFF_H_L  47360    //      -> 51968
#define OFF_SQ_H 42752    // sq^T hi [72 d][68] -> 47648 (aliases h after stage 2)
#define OFF_W2_H 51968    // W2 hi [64 f][36] -> 54272
#define SMEM_WORDS 54272  // 217088 bytes

// ---------------- helpers ----------------
__device__ __forceinline__ void split2(float x, unsigned short& h, unsigned short& l) {
    __half hb = __float2half_rn(x);
    float lf = x - __half2float(hb);
    h = __half_as_ushort(hb);
    l = __half_as_ushort(__float2half_rn(lf));
}
// pairwise fp16 split: hi pair + residual pair
__device__ __forceinline__ void pack8(const float* v, uint4& H, uint4& L) {
    uint32_t* Hp = &H.x;
    uint32_t* Lp = &L.x;
    #pragma unroll
    for (int p = 0; p < 4; p++) {
        float v0 = v[2 * p], v1 = v[2 * p + 1];
        __half2 hh = __floats2half2_rn(v0, v1);
        float h0 = __low2float(hh), h1 = __high2float(hh);
        __half2 ll = __floats2half2_rn(v0 - h0, v1 - h1);
        Hp[p] = *reinterpret_cast<uint32_t*>(&hh);
        Lp[p] = *reinterpret_cast<uint32_t*>(&ll);
    }
}
__device__ __forceinline__ void mma16(float* d, const uint32_t* a, const uint32_t* b) {
    asm volatile(
        "mma.sync.aligned.m16n8k16.row.col.f32.f16.f16.f32 "
        "{%0,%1,%2,%3}, {%4,%5,%6,%7}, {%8,%9}, {%0,%1,%2,%3};"
        : "+f"(d[0]), "+f"(d[1]), "+f"(d[2]), "+f"(d[3])
        : "r"(a[0]), "r"(a[1]), "r"(a[2]), "r"(a[3]), "r"(b[0]), "r"(b[1]));
}
__device__ __forceinline__ void st16s(uint32_t* smu, int word, int half, unsigned short v) {
    ((unsigned short*)&smu[word])[half] = v;
}
__device__ __forceinline__ uint32_t sptr(const void* p) {
    return (uint32_t)__cvta_generic_to_shared(p);
}
#define LDSM4(R0, R1, R2, R3, A) \
    asm volatile("ldmatrix.sync.aligned.m8n8.x4.shared.b16 {%0,%1,%2,%3}, [%4];" \
                 : "=r"(R0), "=r"(R1), "=r"(R2), "=r"(R3) : "r"(A))
#define LDSM2(R0, R1, A) \
    asm volatile("ldmatrix.sync.aligned.m8n8.x2.shared.b16 {%0,%1}, [%2];" \
                 : "=r"(R0), "=r"(R1) : "r"(A))
#define CP16(dst, src) \
    asm volatile("cp.async.cg.shared.global [%0], [%1], 16;" :: "r"(dst), "l"(src))
#define CP_COMMIT() asm volatile("cp.async.commit_group;" ::: "memory")
#define CP_WAIT0()  asm volatile("cp.async.wait_group 0;" ::: "memory")

// ---------------- prep: convert weights once to fp16 hi (chunked) ----------------
__global__ void __launch_bounds__(256) k_prep(const float* __restrict__ W1,
                                              const float* __restrict__ W2,
                                              const float* __restrict__ Wa) {
    int i = blockIdx.x * 256 + threadIdx.x;
    if (i < 24576) {                      // [Wa;W1]: 4 chunks x 192 rows x 32 words
        int c = i / 6144, rem = i % 6144;
        int r = rem >> 5, ww = rem & 31;
        const float* src = (r < 128) ? (Wa + (size_t)r * Dd) : (W1 + (size_t)(r - 128) * Dd);
        __half2 p = __floats2half2_rn(src[c * 64 + 2 * ww], src[c * 64 + 2 * ww + 1]);
        g_WcH[i] = *reinterpret_cast<uint32_t*>(&p);
    } else if (i < 24576 + 2048) {        // W2: 64 rows x 32 words
        int j = i - 24576;
        int r = j >> 5, ww = j & 31;
        __half2 p = __floats2half2_rn(W2[(size_t)r * 64 + 2 * ww], W2[(size_t)r * 64 + 2 * ww + 1]);
        g_W2H[j] = *reinterpret_cast<uint32_t*>(&p);
    }
}

// ---------------- init ----------------
__global__ void __launch_bounds__(256) k_init() {
    int i = blockIdx.x * 256 + threadIdx.x;
    if (i < Bb * Kk * Dc) g_agg[i] = 0.0f;
    else if (i < Bb * Kk * Dc + Bb * Kk) g_mass[i - Bb * Kk * Dc] = 0.0f;
    else if (i < Bb * Kk * Dc + Bb * Kk + Bb) g_ss[i - Bb * Kk * Dc - Bb * Kk] = 0.0f;
}

// ---------------- fused main kernel: one 128-token tile per block, 512 threads ----------------
__global__ void __launch_bounds__(512, 1) k_fused(
    const float* __restrict__ X,  const float* __restrict__ b1,
    const float* __restrict__ b2, const float* __restrict__ ba)
{
    extern __shared__ float smf[];
    uint32_t* smu = (uint32_t*)smf;
    __shared__ float s_ba[128], s_b1[64], s_b2[64];

    const int tid  = threadIdx.x;
    const int w    = tid >> 5;          // 0..15
    const int lane = tid & 31;
    const int ty   = lane >> 2;
    const int tx   = lane & 3;
    const int b    = blockIdx.x >> 5;
    const int n0t  = (blockIdx.x & 31) * 128;

    // ldmatrix lane geometry
    const int matq = lane >> 3, rowq = lane & 7;
    const int mrow  = (matq & 1) * 8 + rowq;
    const int acolw = (matq >> 1) * 4;
    const int nrow  = (matq >> 1) * 8 + rowq;
    const int bcolw = (matq & 1) * 4;

    // ---- prologue: async copies for W2 + W chunk 0, then X fill ----
    {
        int row = tid >> 3, seg = tid & 7;    // tid 0..511 -> 64 rows x 8 segs
        CP16(sptr(&smu[OFF_W2_H + row * 36 + seg * 4]), &g_W2H[row * 32 + seg * 4]);
    }
    #pragma unroll
    for (int it = 0; it < 3; it++) {
        int idx = tid + it * 512;            // 0..1535 -> 192 rows x 8 segs
        int row = idx >> 3, seg = idx & 7;
        CP16(sptr(&smu[OFF_WC_H + row * 36 + seg * 4]), &g_WcH[row * 32 + seg * 4]);
    }
    CP_COMMIT();

    if (tid < 128) s_ba[tid] = ba[tid];
    else if (tid < 192) s_b1[tid - 128] = b1[tid - 128];
    else if (tid < 256) s_b2[tid - 192] = b2[tid - 192];

    // ---- X tile (128x256) split -> fp16 hi/lo (overlaps cp.async loads) ----
    {
        const float4* X4 = (const float4*)(X + (size_t)(b * Nn + n0t) * Dd);
        #pragma unroll
        for (int it = 0; it < 8; it++) {
            int idx = tid + it * 512;            // 0..4095
            int row = idx >> 5, gg = idx & 31;
            float4 f0 = X4[row * 64 + gg * 2], f1 = X4[row * 64 + gg * 2 + 1];
            float v[8] = {f0.x, f0.y, f0.z, f0.w, f1.x, f1.y, f1.z, f1.w};
            uint4 H, L;
            pack8(v, H, L);
            *(uint4*)&smu[OFF_XH + row * 132 + gg * 4] = H;
            *(uint4*)&smu[OFF_XL + row * 132 + gg * 4] = L;
        }
    }

    // ---- stage 1: Y[128 tok, 192] = X @ [Wa;W1]^T  (K=256 in 4 chunks) ----
    const int wm = (w & 3) * 32;
    const int wn = (w >> 2) * 48;
    float acc1[2][6][4];
    #pragma unroll
    for (int mt = 0; mt < 2; mt++)
        #pragma unroll
        for (int nb = 0; nb < 6; nb++)
            #pragma unroll
            for (int q = 0; q < 4; q++) acc1[mt][nb][q] = 0.0f;

    uint32_t aAh[2], aAl[2], aBh[3];
    #pragma unroll
    for (int mt = 0; mt < 2; mt++) {
        aAh[mt] = sptr(&smu[OFF_XH + (wm + mt * 16 + mrow) * 132 + acolw]);
        aAl[mt] = sptr(&smu[OFF_XL + (wm + mt * 16 + mrow) * 132 + acolw]);
    }
    #pragma unroll
    for (int pp = 0; pp < 3; pp++)
        aBh[pp] = sptr(&smu[OFF_WC_H + (wn + pp * 16 + nrow) * 36 + bcolw]);

    for (int c = 0; c < 4; c++) {
        if (c > 0) {
            __syncthreads();   // previous chunk's compute done before overwrite
            #pragma unroll
            for (int it = 0; it < 3; it++) {
                int idx = tid + it * 512;
                int row = idx >> 3, seg = idx & 7;
                CP16(sptr(&smu[OFF_WC_H + row * 36 + seg * 4]),
                     &g_WcH[c * 6144 + row * 32 + seg * 4]);
            }
            CP_COMMIT();
        }
        CP_WAIT0();
        __syncthreads();

        #pragma unroll
        for (int s = 0; s < 4; s++) {
            const uint32_t offA = (uint32_t)(c * 32 + s * 8) * 4;
            const uint32_t offB = (uint32_t)(s * 8) * 4;
            uint32_t ah[2][4], al[2][4];
            LDSM4(ah[0][0], ah[0][1], ah[0][2], ah[0][3], aAh[0] + offA);
            LDSM4(ah[1][0], ah[1][1], ah[1][2], ah[1][3], aAh[1] + offA);
            LDSM4(al[0][0], al[0][1], al[0][2], al[0][3], aAl[0] + offA);
            LDSM4(al[1][0], al[1][1], al[1][2], al[1][3], aAl[1] + offA);
            #pragma unroll
            for (int pp = 0; pp < 3; pp++) {
                uint32_t bh[4];
                LDSM4(bh[0], bh[1], bh[2], bh[3], aBh[pp] + offB);
                #pragma unroll
                for (int e = 0; e < 2; e++) {
                    const int nb = pp * 2 + e;
                    #pragma unroll
                    for (int mt = 0; mt < 2; mt++) {
                        mma16(acc1[mt][nb], ah[mt], bh + e * 2);
                        mma16(acc1[mt][nb], al[mt], bh + e * 2);
                    }
                }
            }
        }
    }
    __syncthreads();

    // ---- write Y column-major [col][tok] (fp32) ----
    #pragma unroll
    for (int mt = 0; mt < 2; mt++)
        #pragma unroll
        for (int nb = 0; nb < 6; nb++) {
            int row = wm + mt * 16 + ty;
            int col = wn + nb * 8 + 2 * tx;
            smf[OFF_Y + col * 132 + row]           = acc1[mt][nb][0];
            smf[OFF_Y + (col + 1) * 132 + row]     = acc1[mt][nb][1];
            smf[OFF_Y + col * 132 + row + 8]       = acc1[mt][nb][2];
            smf[OFF_Y + (col + 1) * 132 + row + 8] = acc1[mt][nb][3];
        }
    __syncthreads();

    // ---- softmax: 4 threads per token; then h-convert: 4 threads per token ----
    {
        const int tok = tid >> 2;
        const int j0 = (tid & 3) * 32;
        float mx = -1e30f;
        #pragma unroll 8
        for (int j = j0; j < j0 + 32; j++)
            mx = fmaxf(mx, smf[OFF_Y + j * 132 + tok] + s_ba[j]);
        mx = fmaxf(mx, __shfl_xor_sync(0xFFFFFFFFu, mx, 1));
        mx = fmaxf(mx, __shfl_xor_sync(0xFFFFFFFFu, mx, 2));
        float ssum = 0.0f;
        #pragma unroll 8
        for (int j = j0; j < j0 + 32; j++) {
            float e = __expf(smf[OFF_Y + j * 132 + tok] + s_ba[j] - mx);
            smf[OFF_Y + j * 132 + tok] = e;
            ssum += e;
        }
        ssum += __shfl_xor_sync(0xFFFFFFFFu, ssum, 1);
        ssum += __shfl_xor_sync(0xFFFFFFFFu, ssum, 2);
        const float inv = 1.0f / ssum;
        const int wrd = tok >> 1, hf = tok & 1;
        #pragma unroll 8
        for (int j = j0; j < j0 + 32; j++) {
            unsigned short hh, ll;
            split2(smf[OFF_Y + j * 132 + tok] * inv, hh, ll);
            st16s(smu, OFF_AT_H + j * 68 + wrd, hf, hh);
            st16s(smu, OFF_AT_L + j * 68 + wrd, hf, ll);
        }
        // h: this thread handles 16 e's of its token (2 groups of 8)
        #pragma unroll
        for (int g2 = 0; g2 < 2; g2++) {
            const int gg = (tid & 3) * 2 + g2;
            float v[8];
            #pragma unroll
            for (int q = 0; q < 8; q++) {
                int e = gg * 8 + q;
                float h = smf[OFF_Y + (128 + e) * 132 + tok] + s_b1[e];
                v[q] = (h >= 0.0f) ? h : 0.01f * h;
            }
            uint4 H, L;
            pack8(v, H, L);
            *(uint4*)&smu[OFF_H_H + tok * 36 + gg * 4] = H;
            *(uint4*)&smu[OFF_H_L + tok * 36 + gg * 4] = L;
        }
    }
    __syncthreads();

    // ---- stage 2: sq[128 tok, 64] = h @ W2^T (K=64); 16 tok x 32 f per warp ----
    const int m2 = (w & 7) * 16;
    const int nsel = w >> 3;            // 0 or 1
    float acc2[4][4];
    #pragma unroll
    for (int nb = 0; nb < 4; nb++)
        #pragma unroll
        for (int q = 0; q < 4; q++) acc2[nb][q] = 0.0f;

    {
        const uint32_t aH2h = sptr(&smu[OFF_H_H + (m2 + mrow) * 36 + acolw]);
        const uint32_t aH2l = sptr(&smu[OFF_H_L + (m2 + mrow) * 36 + acolw]);
        uint32_t aW2h[2];
        #pragma unroll
        for (int pl = 0; pl < 2; pl++)
            aW2h[pl] = sptr(&smu[OFF_W2_H + ((nsel * 2 + pl) * 16 + nrow) * 36 + bcolw]);
        #pragma unroll
        for (int s = 0; s < 4; s++) {
            const uint32_t off = (uint32_t)(s * 8) * 4;
            uint32_t ah[4], al[4];
            LDSM4(ah[0], ah[1], ah[2], ah[3], aH2h + off);
            LDSM4(al[0], al[1], al[2], al[3], aH2l + off);
            #pragma unroll
            for (int pl = 0; pl < 2; pl++) {
                uint32_t bh[4];
                LDSM4(bh[0], bh[1], bh[2], bh[3], aW2h[pl] + off);
                #pragma unroll
                for (int e = 0; e < 2; e++) {
                    const int nb = pl * 2 + e;
                    mma16(acc2[nb], ah, bh + e * 2);
                    mma16(acc2[nb], al, bh + e * 2);
                }
            }
        }
    }
    __syncthreads();   // all stage-2 reads of h done before sq^T overwrites it

    // ---- write sq^T [d][tok] (+b2) fp16 hi; append ones row (d=64) ----
    #pragma unroll
    for (int nb = 0; nb < 4; nb++)
        #pragma unroll
        for (int q = 0; q < 4; q++) {
            int row = m2 + ty + ((q >> 1) << 3);             // token
            int col = nsel * 32 + nb * 8 + 2 * tx + (q & 1); // d
            unsigned short hh =
                __half_as_ushort(__float2half_rn(acc2[nb][q] + s_b2[col]));
            st16s(smu, OFF_SQ_H + col * 68 + (row >> 1), row & 1, hh);
        }
    if (tid < 128) {
        const int tok = tid, wrd = tok >> 1, hf = tok & 1;
        st16s(smu, OFF_SQ_H + 64 * 68 + wrd, hf, (unsigned short)0x3C00);  // fp16 1.0
        #pragma unroll
        for (int rr = 65; rr < 72; rr++)
            st16s(smu, OFF_SQ_H + rr * 68 + wrd, hf, 0);
    }
    __syncthreads();

    // ---- stage 3: D3[128 cl, 72] = assign^T @ [sq | 1]  (K=128 tokens) ----
    float acc3[4][4];
    float acc3m[4];
    #pragma unroll
    for (int nb = 0; nb < 4; nb++)
        #pragma unroll
        for (int q = 0; q < 4; q++) acc3[nb][q] = 0.0f;
    #pragma unroll
    for (int q = 0; q < 4; q++) acc3m[q] = 0.0f;

    {
        const uint32_t aA3h = sptr(&smu[OFF_AT_H + (m2 + mrow) * 68 + acolw]);
        const uint32_t aA3l = sptr(&smu[OFF_AT_L + (m2 + mrow) * 68 + acolw]);
        uint32_t aB3h[2];
        #pragma unroll
        for (int pl = 0; pl < 2; pl++)
            aB3h[pl] = sptr(&smu[OFF_SQ_H + ((nsel * 2 + pl) * 16 + nrow) * 68 + bcolw]);
        const int mat2 = (lane >> 3) & 1;
        const uint32_t aB9h = sptr(&smu[OFF_SQ_H + (64 + rowq) * 68 + mat2 * 4]);

        #pragma unroll
        for (int s = 0; s < 8; s++) {
            const uint32_t off = (uint32_t)(s * 8) * 4;
            uint32_t ah[4], al[4];
            LDSM4(ah[0], ah[1], ah[2], ah[3], aA3h + off);
            LDSM4(al[0], al[1], al[2], al[3], aA3l + off);
            #pragma unroll
            for (int pl = 0; pl < 2; pl++) {
                uint32_t bh[4];
                LDSM4(bh[0], bh[1], bh[2], bh[3], aB3h[pl] + off);
                #pragma unroll
                for (int e = 0; e < 2; e++) {
                    const int nb = pl * 2 + e;
                    mma16(acc3[nb], ah, bh + e * 2);
                    mma16(acc3[nb], al, bh + e * 2);
                }
            }
            if (nsel) {
                uint32_t b9h[2];
                LDSM2(b9h[0], b9h[1], aB9h + off);
                mma16(acc3m, ah, b9h);
                mma16(acc3m, al, b9h);
            }
        }
    }

    // ---- epilogue: atomics ----
    {
        const size_t base0 = ((size_t)b * Kk + m2 + ty) * Dc;
        #pragma unroll
        for (int nb = 0; nb < 4; nb++) {
            int d0 = nsel * 32 + nb * 8 + 2 * tx;
            atomicAdd(&g_agg[base0 + d0],              acc3[nb][0]);
            atomicAdd(&g_agg[base0 + d0 + 1],          acc3[nb][1]);
            atomicAdd(&g_agg[base0 + 8 * Dc + d0],     acc3[nb][2]);
            atomicAdd(&g_agg[base0 + 8 * Dc + d0 + 1], acc3[nb][3]);
        }
        if (nsel && tx == 0) {
            atomicAdd(&g_mass[b * Kk + m2 + ty],     acc3m[0]);
            atomicAdd(&g_mass[b * Kk + m2 + ty + 8], acc3m[2]);
        }
    }
}

// ---------------- finalize, pass 1: vlad + partial sum-of-squares ----------------
__global__ void __launch_bounds__(256) k_vlad(const float* __restrict__ centroid,
                                              float* __restrict__ out) {
    const int b = blockIdx.x;
    const int seg = blockIdx.y;
    const int i = seg * 1024 + threadIdx.x * 4;
    const size_t gi = (size_t)b * (Kk * Dc) + i;
    const int k = i >> 6;
    const float m = g_mass[b * Kk + k];
    float4 a = *(const float4*)&g_agg[gi];
    float4 c = *(const float4*)&centroid[i];
    float4 v;
    v.x = a.x - m * c.x;
    v.y = a.y - m * c.y;
    v.z = a.z - m * c.z;
    v.w = a.w - m * c.w;
    *(float4*)&out[gi] = v;
    float ss = v.x * v.x + v.y * v.y + v.z * v.z + v.w * v.w;
    #pragma unroll
    for (int d = 16; d > 0; d >>= 1) ss += __shfl_xor_sync(0xFFFFFFFFu, ss, d);
    if ((threadIdx.x & 31) == 0) atomicAdd(&g_ss[b], ss);
}

// ---------------- finalize, pass 2: scale by 1/max(norm, eps) ----------------
__global__ void __launch_bounds__(256) k_scale(float* __restrict__ out) {
    const int b = blockIdx.x;
    const float n = sqrtf(g_ss[b]);
    const float inv = 1.0f / fmaxf(n, 1e-12f);
    const int i = blockIdx.y * 1024 + threadIdx.x * 4;
    const size_t gi = (size_t)b * (Kk * Dc) + i;
    float4 v = *(float4*)&out[gi];
    v.x *= inv; v.y *= inv; v.z *= inv; v.w *= inv;
    *(float4*)&out[gi] = v;
}

// ---------------- launch ----------------
extern "C" void kernel_launch(void* const* d_in, const int* in_sizes, int n_in,
                              void* d_out, int out_size) {
    const float* X        = (const float*)d_in[0];
    const float* W1       = (const float*)d_in[1];
    const float* b1       = (const float*)d_in[2];
    const float* W2       = (const float*)d_in[3];
    const float* b2       = (const float*)d_in[4];
    const float* Wa       = (const float*)d_in[5];
    const float* ba       = (const float*)d_in[6];
    const float* centroid = (const float*)d_in[7];
    float* out = (float*)d_out;

    cudaFuncSetAttribute(k_fused, cudaFuncAttributeMaxDynamicSharedMemorySize,
                         SMEM_WORDS * 4);

    k_prep<<<104, 256>>>(W1, W2, Wa);
    k_init<<<1041, 256>>>();
    k_fused<<<1024, 512, SMEM_WORDS * 4>>>(X, b1, b2, ba);
    dim3 gn(Bb, 8);
    k_vlad<<<gn, 256>>>(centroid, out);
    k_scale<<<gn, 256>>>(out);
}

// round 16
// speedup vs baseline: 1.6027x; 1.1611x over previous
#include <cuda_runtime.h>
#include <cuda_fp16.h>
#include <math.h>
#include <stdint.h>

#define Bb 32
#define Nn 4096
#define Dd 256
#define Kk 128
#define Dc 64

// ---------------- device scratch ----------------
__device__ float g_agg[(size_t)Bb * Kk * Dc];
__device__ float g_mass[Bb * Kk];
__device__ float g_ss[Bb];
// pre-split weights, fp16 hi packed 2-per-word, chunked to match smem layout
__device__ __align__(16) uint32_t g_WcH[4 * 192 * 32];
__device__ __align__(16) uint32_t g_W2H[64 * 32];

// ---------------- smem word-offset layout (32-bit words) ----------------
#define OFF_XH   0        // X hi  [128 tok][132] -> 16896
#define OFF_WC_H 16896    // W chunk hi [192 row][36] -> 23808
#define OFF_Y    0        // Y fp32 col-major [192 col][132 tok] -> 25344
#define OFF_AT_H 25344    // assign^T hi [128 cl][68] -> 34048
#define OFF_AT_L 34048    //             -> 42752
#define OFF_H_H  42752    // h hi [128 tok][36] -> 47360
#define OFF_H_L  47360    //      -> 51968
#define OFF_SQ_H 42752    // sq^T hi [72 d][68] -> 47648 (aliases h after stage 2)
#define OFF_W2_H 51968    // W2 hi [64 f][36] -> 54272
#define SMEM_WORDS 54272  // 217088 bytes

// ---------------- helpers ----------------
__device__ __forceinline__ void split2(float x, unsigned short& h, unsigned short& l) {
    __half hb = __float2half_rn(x);
    float lf = x - __half2float(hb);
    h = __half_as_ushort(hb);
    l = __half_as_ushort(__float2half_rn(lf));
}
// pairwise fp16 split: hi pair + residual pair
__device__ __forceinline__ void pack8(const float* v, uint4& H, uint4& L) {
    uint32_t* Hp = &H.x;
    uint32_t* Lp = &L.x;
    #pragma unroll
    for (int p = 0; p < 4; p++) {
        float v0 = v[2 * p], v1 = v[2 * p + 1];
        __half2 hh = __floats2half2_rn(v0, v1);
        float h0 = __low2float(hh), h1 = __high2float(hh);
        __half2 ll = __floats2half2_rn(v0 - h0, v1 - h1);
        Hp[p] = *reinterpret_cast<uint32_t*>(&hh);
        Lp[p] = *reinterpret_cast<uint32_t*>(&ll);
    }
}
// hi-only pack
__device__ __forceinline__ void pack8h(const float* v, uint4& H) {
    uint32_t* Hp = &H.x;
    #pragma unroll
    for (int p = 0; p < 4; p++) {
        __half2 hh = __floats2half2_rn(v[2 * p], v[2 * p + 1]);
        Hp[p] = *reinterpret_cast<uint32_t*>(&hh);
    }
}
__device__ __forceinline__ void mma16(float* d, const uint32_t* a, const uint32_t* b) {
    asm volatile(
        "mma.sync.aligned.m16n8k16.row.col.f32.f16.f16.f32 "
        "{%0,%1,%2,%3}, {%4,%5,%6,%7}, {%8,%9}, {%0,%1,%2,%3};"
        : "+f"(d[0]), "+f"(d[1]), "+f"(d[2]), "+f"(d[3])
        : "r"(a[0]), "r"(a[1]), "r"(a[2]), "r"(a[3]), "r"(b[0]), "r"(b[1]));
}
__device__ __forceinline__ void st16s(uint32_t* smu, int word, int half, unsigned short v) {
    ((unsigned short*)&smu[word])[half] = v;
}
__device__ __forceinline__ uint32_t sptr(const void* p) {
    return (uint32_t)__cvta_generic_to_shared(p);
}
#define LDSM4(R0, R1, R2, R3, A) \
    asm volatile("ldmatrix.sync.aligned.m8n8.x4.shared.b16 {%0,%1,%2,%3}, [%4];" \
                 : "=r"(R0), "=r"(R1), "=r"(R2), "=r"(R3) : "r"(A))
#define LDSM2(R0, R1, A) \
    asm volatile("ldmatrix.sync.aligned.m8n8.x2.shared.b16 {%0,%1}, [%2];" \
                 : "=r"(R0), "=r"(R1) : "r"(A))
#define CP16(dst, src) \
    asm volatile("cp.async.cg.shared.global [%0], [%1], 16;" :: "r"(dst), "l"(src))
#define CP_COMMIT() asm volatile("cp.async.commit_group;" ::: "memory")
#define CP_WAIT0()  asm volatile("cp.async.wait_group 0;" ::: "memory")

// ---------------- prep: convert weights once to fp16 hi (chunked) ----------------
__global__ void __launch_bounds__(256) k_prep(const float* __restrict__ W1,
                                              const float* __restrict__ W2,
                                              const float* __restrict__ Wa) {
    int i = blockIdx.x * 256 + threadIdx.x;
    if (i < 24576) {                      // [Wa;W1]: 4 chunks x 192 rows x 32 words
        int c = i / 6144, rem = i % 6144;
        int r = rem >> 5, ww = rem & 31;
        const float* src = (r < 128) ? (Wa + (size_t)r * Dd) : (W1 + (size_t)(r - 128) * Dd);
        __half2 p = __floats2half2_rn(src[c * 64 + 2 * ww], src[c * 64 + 2 * ww + 1]);
        g_WcH[i] = *reinterpret_cast<uint32_t*>(&p);
    } else if (i < 24576 + 2048) {        // W2: 64 rows x 32 words
        int j = i - 24576;
        int r = j >> 5, ww = j & 31;
        __half2 p = __floats2half2_rn(W2[(size_t)r * 64 + 2 * ww], W2[(size_t)r * 64 + 2 * ww + 1]);
        g_W2H[j] = *reinterpret_cast<uint32_t*>(&p);
    }
}

// ---------------- init ----------------
__global__ void __launch_bounds__(256) k_init() {
    int i = blockIdx.x * 256 + threadIdx.x;
    if (i < Bb * Kk * Dc) g_agg[i] = 0.0f;
    else if (i < Bb * Kk * Dc + Bb * Kk) g_mass[i - Bb * Kk * Dc] = 0.0f;
    else if (i < Bb * Kk * Dc + Bb * Kk + Bb) g_ss[i - Bb * Kk * Dc - Bb * Kk] = 0.0f;
}

// ---------------- fused main kernel: one 128-token tile per block, 512 threads ----------------
__global__ void __launch_bounds__(512, 1) k_fused(
    const float* __restrict__ X,  const float* __restrict__ b1,
    const float* __restrict__ b2, const float* __restrict__ ba)
{
    extern __shared__ float smf[];
    uint32_t* smu = (uint32_t*)smf;
    __shared__ float s_ba[128], s_b1[64], s_b2[64];

    const int tid  = threadIdx.x;
    const int w    = tid >> 5;          // 0..15
    const int lane = tid & 31;
    const int ty   = lane >> 2;
    const int tx   = lane & 3;
    const int b    = blockIdx.x >> 5;
    const int n0t  = (blockIdx.x & 31) * 128;

    // ldmatrix lane geometry
    const int matq = lane >> 3, rowq = lane & 7;
    const int mrow  = (matq & 1) * 8 + rowq;
    const int acolw = (matq >> 1) * 4;
    const int nrow  = (matq >> 1) * 8 + rowq;
    const int bcolw = (matq & 1) * 4;

    // ---- prologue: async copies for W2 + W chunk 0, then X fill ----
    {
        int row = tid >> 3, seg = tid & 7;    // tid 0..511 -> 64 rows x 8 segs
        CP16(sptr(&smu[OFF_W2_H + row * 36 + seg * 4]), &g_W2H[row * 32 + seg * 4]);
    }
    #pragma unroll
    for (int it = 0; it < 3; it++) {
        int idx = tid + it * 512;            // 0..1535 -> 192 rows x 8 segs
        int row = idx >> 3, seg = idx & 7;
        CP16(sptr(&smu[OFF_WC_H + row * 36 + seg * 4]), &g_WcH[row * 32 + seg * 4]);
    }
    CP_COMMIT();

    if (tid < 128) s_ba[tid] = ba[tid];
    else if (tid < 192) s_b1[tid - 128] = b1[tid - 128];
    else if (tid < 256) s_b2[tid - 192] = b2[tid - 192];

    // ---- X tile (128x256) -> fp16 hi only (overlaps cp.async loads) ----
    {
        const float4* X4 = (const float4*)(X + (size_t)(b * Nn + n0t) * Dd);
        #pragma unroll
        for (int it = 0; it < 8; it++) {
            int idx = tid + it * 512;            // 0..4095
            int row = idx >> 5, gg = idx & 31;
            float4 f0 = X4[row * 64 + gg * 2], f1 = X4[row * 64 + gg * 2 + 1];
            float v[8] = {f0.x, f0.y, f0.z, f0.w, f1.x, f1.y, f1.z, f1.w};
            uint4 H;
            pack8h(v, H);
            *(uint4*)&smu[OFF_XH + row * 132 + gg * 4] = H;
        }
    }

    // ---- stage 1: Y[128 tok, 192] = X @ [Wa;W1]^T  (K=256 in 4 chunks) ----
    const int wm = (w & 3) * 32;
    const int wn = (w >> 2) * 48;
    float acc1[2][6][4];
    #pragma unroll
    for (int mt = 0; mt < 2; mt++)
        #pragma unroll
        for (int nb = 0; nb < 6; nb++)
            #pragma unroll
            for (int q = 0; q < 4; q++) acc1[mt][nb][q] = 0.0f;

    uint32_t aAh[2], aBh[3];
    #pragma unroll
    for (int mt = 0; mt < 2; mt++)
        aAh[mt] = sptr(&smu[OFF_XH + (wm + mt * 16 + mrow) * 132 + acolw]);
    #pragma unroll
    for (int pp = 0; pp < 3; pp++)
        aBh[pp] = sptr(&smu[OFF_WC_H + (wn + pp * 16 + nrow) * 36 + bcolw]);

    for (int c = 0; c < 4; c++) {
        if (c > 0) {
            __syncthreads();   // previous chunk's compute done before overwrite
            #pragma unroll
            for (int it = 0; it < 3; it++) {
                int idx = tid + it * 512;
                int row = idx >> 3, seg = idx & 7;
                CP16(sptr(&smu[OFF_WC_H + row * 36 + seg * 4]),
                     &g_WcH[c * 6144 + row * 32 + seg * 4]);
            }
            CP_COMMIT();
        }
        CP_WAIT0();
        __syncthreads();

        #pragma unroll
        for (int s = 0; s < 4; s++) {
            const uint32_t offA = (uint32_t)(c * 32 + s * 8) * 4;
            const uint32_t offB = (uint32_t)(s * 8) * 4;
            uint32_t ah[2][4];
            LDSM4(ah[0][0], ah[0][1], ah[0][2], ah[0][3], aAh[0] + offA);
            LDSM4(ah[1][0], ah[1][1], ah[1][2], ah[1][3], aAh[1] + offA);
            #pragma unroll
            for (int pp = 0; pp < 3; pp++) {
                uint32_t bh[4];
                LDSM4(bh[0], bh[1], bh[2], bh[3], aBh[pp] + offB);
                #pragma unroll
                for (int e = 0; e < 2; e++) {
                    const int nb = pp * 2 + e;
                    #pragma unroll
                    for (int mt = 0; mt < 2; mt++)
                        mma16(acc1[mt][nb], ah[mt], bh + e * 2);
                }
            }
        }
    }
    __syncthreads();

    // ---- write Y column-major [col][tok] (fp32) ----
    #pragma unroll
    for (int mt = 0; mt < 2; mt++)
        #pragma unroll
        for (int nb = 0; nb < 6; nb++) {
            int row = wm + mt * 16 + ty;
            int col = wn + nb * 8 + 2 * tx;
            smf[OFF_Y + col * 132 + row]           = acc1[mt][nb][0];
            smf[OFF_Y + (col + 1) * 132 + row]     = acc1[mt][nb][1];
            smf[OFF_Y + col * 132 + row + 8]       = acc1[mt][nb][2];
            smf[OFF_Y + (col + 1) * 132 + row + 8] = acc1[mt][nb][3];
        }
    __syncthreads();

    // ---- softmax: 4 threads per token; then h-convert: 4 threads per token ----
    {
        const int tok = tid >> 2;
        const int j0 = (tid & 3) * 32;
        float mx = -1e30f;
        #pragma unroll 8
        for (int j = j0; j < j0 + 32; j++)
            mx = fmaxf(mx, smf[OFF_Y + j * 132 + tok] + s_ba[j]);
        mx = fmaxf(mx, __shfl_xor_sync(0xFFFFFFFFu, mx, 1));
        mx = fmaxf(mx, __shfl_xor_sync(0xFFFFFFFFu, mx, 2));
        float ssum = 0.0f;
        #pragma unroll 8
        for (int j = j0; j < j0 + 32; j++) {
            float e = __expf(smf[OFF_Y + j * 132 + tok] + s_ba[j] - mx);
            smf[OFF_Y + j * 132 + tok] = e;
            ssum += e;
        }
        ssum += __shfl_xor_sync(0xFFFFFFFFu, ssum, 1);
        ssum += __shfl_xor_sync(0xFFFFFFFFu, ssum, 2);
        const float inv = 1.0f / ssum;
        const int wrd = tok >> 1, hf = tok & 1;
        #pragma unroll 8
        for (int j = j0; j < j0 + 32; j++) {
            unsigned short hh, ll;
            split2(smf[OFF_Y + j * 132 + tok] * inv, hh, ll);
            st16s(smu, OFF_AT_H + j * 68 + wrd, hf, hh);
            st16s(smu, OFF_AT_L + j * 68 + wrd, hf, ll);
        }
        // h: this thread handles 16 e's of its token (2 groups of 8)
        #pragma unroll
        for (int g2 = 0; g2 < 2; g2++) {
            const int gg = (tid & 3) * 2 + g2;
            float v[8];
            #pragma unroll
            for (int q = 0; q < 8; q++) {
                int e = gg * 8 + q;
                float h = smf[OFF_Y + (128 + e) * 132 + tok] + s_b1[e];
                v[q] = (h >= 0.0f) ? h : 0.01f * h;
            }
            uint4 H, L;
            pack8(v, H, L);
            *(uint4*)&smu[OFF_H_H + tok * 36 + gg * 4] = H;
            *(uint4*)&smu[OFF_H_L + tok * 36 + gg * 4] = L;
        }
    }
    __syncthreads();

    // ---- stage 2: sq[128 tok, 64] = h @ W2^T (K=64); 16 tok x 32 f per warp ----
    const int m2 = (w & 7) * 16;
    const int nsel = w >> 3;            // 0 or 1
    float acc2[4][4];
    #pragma unroll
    for (int nb = 0; nb < 4; nb++)
        #pragma unroll
        for (int q = 0; q < 4; q++) acc2[nb][q] = 0.0f;

    {
        const uint32_t aH2h = sptr(&smu[OFF_H_H + (m2 + mrow) * 36 + acolw]);
        const uint32_t aH2l = sptr(&smu[OFF_H_L + (m2 + mrow) * 36 + acolw]);
        uint32_t aW2h[2];
        #pragma unroll
        for (int pl = 0; pl < 2; pl++)
            aW2h[pl] = sptr(&smu[OFF_W2_H + ((nsel * 2 + pl) * 16 + nrow) * 36 + bcolw]);
        #pragma unroll
        for (int s = 0; s < 4; s++) {
            const uint32_t off = (uint32_t)(s * 8) * 4;
            uint32_t ah[4], al[4];
            LDSM4(ah[0], ah[1], ah[2], ah[3], aH2h + off);
            LDSM4(al[0], al[1], al[2], al[3], aH2l + off);
            #pragma unroll
            for (int pl = 0; pl < 2; pl++) {
                uint32_t bh[4];
                LDSM4(bh[0], bh[1], bh[2], bh[3], aW2h[pl] + off);
                #pragma unroll
                for (int e = 0; e < 2; e++) {
                    const int nb = pl * 2 + e;
                    mma16(acc2[nb], ah, bh + e * 2);
                    mma16(acc2[nb], al, bh + e * 2);
                }
            }
        }
    }
    __syncthreads();   // all stage-2 reads of h done before sq^T overwrites it

    // ---- write sq^T [d][tok] (+b2) fp16 hi; append ones row (d=64) ----
    #pragma unroll
    for (int nb = 0; nb < 4; nb++)
        #pragma unroll
        for (int q = 0; q < 4; q++) {
            int row = m2 + ty + ((q >> 1) << 3);             // token
            int col = nsel * 32 + nb * 8 + 2 * tx + (q & 1); // d
            unsigned short hh =
                __half_as_ushort(__float2half_rn(acc2[nb][q] + s_b2[col]));
            st16s(smu, OFF_SQ_H + col * 68 + (row >> 1), row & 1, hh);
        }
    if (tid < 128) {
        const int tok = tid, wrd = tok >> 1, hf = tok & 1;
        st16s(smu, OFF_SQ_H + 64 * 68 + wrd, hf, (unsigned short)0x3C00);  // fp16 1.0
        #pragma unroll
        for (int rr = 65; rr < 72; rr++)
            st16s(smu, OFF_SQ_H + rr * 68 + wrd, hf, 0);
    }
    __syncthreads();

    // ---- stage 3: D3[128 cl, 72] = assign^T @ [sq | 1]  (K=128 tokens) ----
    float acc3[4][4];
    float acc3m[4];
    #pragma unroll
    for (int nb = 0; nb < 4; nb++)
        #pragma unroll
        for (int q = 0; q < 4; q++) acc3[nb][q] = 0.0f;
    #pragma unroll
    for (int q = 0; q < 4; q++) acc3m[q] = 0.0f;

    {
        const uint32_t aA3h = sptr(&smu[OFF_AT_H + (m2 + mrow) * 68 + acolw]);
        const uint32_t aA3l = sptr(&smu[OFF_AT_L + (m2 + mrow) * 68 + acolw]);
        uint32_t aB3h[2];
        #pragma unroll
        for (int pl = 0; pl < 2; pl++)
            aB3h[pl] = sptr(&smu[OFF_SQ_H + ((nsel * 2 + pl) * 16 + nrow) * 68 + bcolw]);
        const int mat2 = (lane >> 3) & 1;
        const uint32_t aB9h = sptr(&smu[OFF_SQ_H + (64 + rowq) * 68 + mat2 * 4]);

        #pragma unroll
        for (int s = 0; s < 8; s++) {
            const uint32_t off = (uint32_t)(s * 8) * 4;
            uint32_t ah[4], al[4];
            LDSM4(ah[0], ah[1], ah[2], ah[3], aA3h + off);
            LDSM4(al[0], al[1], al[2], al[3], aA3l + off);
            #pragma unroll
            for (int pl = 0; pl < 2; pl++) {
                uint32_t bh[4];
                LDSM4(bh[0], bh[1], bh[2], bh[3], aB3h[pl] + off);
                #pragma unroll
                for (int e = 0; e < 2; e++) {
                    const int nb = pl * 2 + e;
                    mma16(acc3[nb], ah, bh + e * 2);
                    mma16(acc3[nb], al, bh + e * 2);
                }
            }
            if (nsel) {
                uint32_t b9h[2];
                LDSM2(b9h[0], b9h[1], aB9h + off);
                mma16(acc3m, ah, b9h);
                mma16(acc3m, al, b9h);
            }
        }
    }

    // ---- epilogue: atomics ----
    {
        const size_t base0 = ((size_t)b * Kk + m2 + ty) * Dc;
        #pragma unroll
        for (int nb = 0; nb < 4; nb++) {
            int d0 = nsel * 32 + nb * 8 + 2 * tx;
            atomicAdd(&g_agg[base0 + d0],              acc3[nb][0]);
            atomicAdd(&g_agg[base0 + d0 + 1],          acc3[nb][1]);
            atomicAdd(&g_agg[base0 + 8 * Dc + d0],     acc3[nb][2]);
            atomicAdd(&g_agg[base0 + 8 * Dc + d0 + 1], acc3[nb][3]);
        }
        if (nsel && tx == 0) {
            atomicAdd(&g_mass[b * Kk + m2 + ty],     acc3m[0]);
            atomicAdd(&g_mass[b * Kk + m2 + ty + 8], acc3m[2]);
        }
    }
}

// ---------------- finalize, pass 1: vlad + partial sum-of-squares ----------------
__global__ void __launch_bounds__(256) k_vlad(const float* __restrict__ centroid,
                                              float* __restrict__ out) {
    const int b = blockIdx.x;
    const int seg = blockIdx.y;
    const int i = seg * 1024 + threadIdx.x * 4;
    const size_t gi = (size_t)b * (Kk * Dc) + i;
    const int k = i >> 6;
    const float m = g_mass[b * Kk + k];
    float4 a = *(const float4*)&g_agg[gi];
    float4 c = *(const float4*)&centroid[i];
    float4 v;
    v.x = a.x - m * c.x;
    v.y = a.y - m * c.y;
    v.z = a.z - m * c.z;
    v.w = a.w - m * c.w;
    *(float4*)&out[gi] = v;
    float ss = v.x * v.x + v.y * v.y + v.z * v.z + v.w * v.w;
    #pragma unroll
    for (int d = 16; d > 0; d >>= 1) ss += __shfl_xor_sync(0xFFFFFFFFu, ss, d);
    if ((threadIdx.x & 31) == 0) atomicAdd(&g_ss[b], ss);
}

// ---------------- finalize, pass 2: scale by 1/max(norm, eps) ----------------
__global__ void __launch_bounds__(256) k_scale(float* __restrict__ out) {
    const int b = blockIdx.x;
    const float n = sqrtf(g_ss[b]);
    const float inv = 1.0f / fmaxf(n, 1e-12f);
    const int i = blockIdx.y * 1024 + threadIdx.x * 4;
    const size_t gi = (size_t)b * (Kk * Dc) + i;
    float4 v = *(float4*)&out[gi];
    v.x *= inv; v.y *= inv; v.z *= inv; v.w *= inv;
    *(float4*)&out[gi] = v;
}

// ---------------- launch ----------------
extern "C" void kernel_launch(void* const* d_in, const int* in_sizes, int n_in,
                              void* d_out, int out_size) {
    const float* X        = (const float*)d_in[0];
    const float* W1       = (const float*)d_in[1];
    const float* b1       = (const float*)d_in[2];
    const float* W2       = (const float*)d_in[3];
    const float* b2       = (const float*)d_in[4];
    const float* Wa       = (const float*)d_in[5];
    const float* ba       = (const float*)d_in[6];
    const float* centroid = (const float*)d_in[7];
    float* out = (float*)d_out;

    cudaFuncSetAttribute(k_fused, cudaFuncAttributeMaxDynamicSharedMemorySize,
                         SMEM_WORDS * 4);

    k_prep<<<104, 256>>>(W1, W2, Wa);
    k_init<<<1041, 256>>>();
    k_fused<<<1024, 512, SMEM_WORDS * 4>>>(X, b1, b2, ba);
    dim3 gn(Bb, 8);
    k_vlad<<<gn, 256>>>(centroid, out);
    k_scale<<<gn, 256>>>(out);
}

// round 17
// speedup vs baseline: 1.8469x; 1.1523x over previous
#include <cuda_runtime.h>
#include <cuda_fp16.h>
#include <math.h>
#include <stdint.h>

#define Bb 32
#define Nn 4096
#define Dd 256
#define Kk 128
#define Dc 64

// ---------------- device scratch ----------------
__device__ float g_agg[(size_t)Bb * Kk * Dc];
__device__ float g_mass[Bb * Kk];
__device__ float g_ss[Bb];
// pre-converted weights, fp16 packed 2-per-word, chunked to match smem layout
__device__ __align__(16) uint32_t g_WcH[4 * 192 * 32];
__device__ __align__(16) uint32_t g_W2H[64 * 32];

// ---------------- smem word-offset layout (32-bit words) ----------------
#define OFF_XH   0        // X hi  [128 tok][132] -> 16896
#define OFF_WC_H 16896    // W chunk hi [192 row][36] -> 23808
#define OFF_Y    0        // Y fp32 col-major [192 col][132 tok] -> 25344
#define OFF_AT_H 25344    // assign^T fp16 [128 cl][68] -> 34048
#define OFF_H_H  34048    // h fp16 [128 tok][36] -> 38656
#define OFF_SQ_H 34048    // sq^T fp16 [72 d][68] -> 38944 (aliases h after stage 2)
#define OFF_W2_H 38944    // W2 fp16 [64 f][36] -> 41248
#define SMEM_WORDS 41248  // 164992 bytes

// ---------------- helpers ----------------
// hi-only pack of 8 floats -> 4 packed fp16x2 words
__device__ __forceinline__ void pack8h(const float* v, uint4& H) {
    uint32_t* Hp = &H.x;
    #pragma unroll
    for (int p = 0; p < 4; p++) {
        __half2 hh = __floats2half2_rn(v[2 * p], v[2 * p + 1]);
        Hp[p] = *reinterpret_cast<uint32_t*>(&hh);
    }
}
__device__ __forceinline__ void mma16(float* d, const uint32_t* a, const uint32_t* b) {
    asm volatile(
        "mma.sync.aligned.m16n8k16.row.col.f32.f16.f16.f32 "
        "{%0,%1,%2,%3}, {%4,%5,%6,%7}, {%8,%9}, {%0,%1,%2,%3};"
        : "+f"(d[0]), "+f"(d[1]), "+f"(d[2]), "+f"(d[3])
        : "r"(a[0]), "r"(a[1]), "r"(a[2]), "r"(a[3]), "r"(b[0]), "r"(b[1]));
}
__device__ __forceinline__ void st16s(uint32_t* smu, int word, int half, unsigned short v) {
    ((unsigned short*)&smu[word])[half] = v;
}
__device__ __forceinline__ uint32_t sptr(const void* p) {
    return (uint32_t)__cvta_generic_to_shared(p);
}
#define LDSM4(R0, R1, R2, R3, A) \
    asm volatile("ldmatrix.sync.aligned.m8n8.x4.shared.b16 {%0,%1,%2,%3}, [%4];" \
                 : "=r"(R0), "=r"(R1), "=r"(R2), "=r"(R3) : "r"(A))
#define LDSM2(R0, R1, A) \
    asm volatile("ldmatrix.sync.aligned.m8n8.x2.shared.b16 {%0,%1}, [%2];" \
                 : "=r"(R0), "=r"(R1) : "r"(A))
#define CP16(dst, src) \
    asm volatile("cp.async.cg.shared.global [%0], [%1], 16;" :: "r"(dst), "l"(src))
#define CP_COMMIT() asm volatile("cp.async.commit_group;" ::: "memory")
#define CP_WAIT0()  asm volatile("cp.async.wait_group 0;" ::: "memory")

// ---------------- setup: zero accumulators + convert weights (one launch) ----------------
__global__ void __launch_bounds__(256) k_setup(const float* __restrict__ W1,
                                               const float* __restrict__ W2,
                                               const float* __restrict__ Wa) {
    int i = blockIdx.x * 256 + threadIdx.x;
    if (i < Bb * Kk * Dc) g_agg[i] = 0.0f;
    else if (i < Bb * Kk * Dc + Bb * Kk) g_mass[i - Bb * Kk * Dc] = 0.0f;
    else if (i < Bb * Kk * Dc + Bb * Kk + Bb) g_ss[i - Bb * Kk * Dc - Bb * Kk] = 0.0f;

    if (i < 24576) {                      // [Wa;W1]: 4 chunks x 192 rows x 32 words
        int c = i / 6144, rem = i % 6144;
        int r = rem >> 5, ww = rem & 31;
        const float* src = (r < 128) ? (Wa + (size_t)r * Dd) : (W1 + (size_t)(r - 128) * Dd);
        __half2 p = __floats2half2_rn(src[c * 64 + 2 * ww], src[c * 64 + 2 * ww + 1]);
        g_WcH[i] = *reinterpret_cast<uint32_t*>(&p);
    } else if (i < 24576 + 2048) {        // W2: 64 rows x 32 words
        int j = i - 24576;
        int r = j >> 5, ww = j & 31;
        __half2 p = __floats2half2_rn(W2[(size_t)r * 64 + 2 * ww], W2[(size_t)r * 64 + 2 * ww + 1]);
        g_W2H[j] = *reinterpret_cast<uint32_t*>(&p);
    }
}

// ---------------- fused main kernel: one 128-token tile per block, 512 threads ----------------
__global__ void __launch_bounds__(512, 1) k_fused(
    const float* __restrict__ X,  const float* __restrict__ b1,
    const float* __restrict__ b2, const float* __restrict__ ba)
{
    extern __shared__ float smf[];
    uint32_t* smu = (uint32_t*)smf;
    __shared__ float s_ba[128], s_b1[64], s_b2[64];

    const int tid  = threadIdx.x;
    const int w    = tid >> 5;          // 0..15
    const int lane = tid & 31;
    const int ty   = lane >> 2;
    const int tx   = lane & 3;
    const int b    = blockIdx.x >> 5;
    const int n0t  = (blockIdx.x & 31) * 128;

    // ldmatrix lane geometry
    const int matq = lane >> 3, rowq = lane & 7;
    const int mrow  = (matq & 1) * 8 + rowq;
    const int acolw = (matq >> 1) * 4;
    const int nrow  = (matq >> 1) * 8 + rowq;
    const int bcolw = (matq & 1) * 4;

    // ---- prologue: async copies for W2 + W chunk 0, then X fill ----
    {
        int row = tid >> 3, seg = tid & 7;    // tid 0..511 -> 64 rows x 8 segs
        CP16(sptr(&smu[OFF_W2_H + row * 36 + seg * 4]), &g_W2H[row * 32 + seg * 4]);
    }
    #pragma unroll
    for (int it = 0; it < 3; it++) {
        int idx = tid + it * 512;            // 0..1535 -> 192 rows x 8 segs
        int row = idx >> 3, seg = idx & 7;
        CP16(sptr(&smu[OFF_WC_H + row * 36 + seg * 4]), &g_WcH[row * 32 + seg * 4]);
    }
    CP_COMMIT();

    if (tid < 128) s_ba[tid] = ba[tid];
    else if (tid < 192) s_b1[tid - 128] = b1[tid - 128];
    else if (tid < 256) s_b2[tid - 192] = b2[tid - 192];

    // ---- X tile (128x256) -> fp16 hi only (overlaps cp.async loads) ----
    {
        const float4* X4 = (const float4*)(X + (size_t)(b * Nn + n0t) * Dd);
        #pragma unroll
        for (int it = 0; it < 8; it++) {
            int idx = tid + it * 512;            // 0..4095
            int row = idx >> 5, gg = idx & 31;
            float4 f0 = X4[row * 64 + gg * 2], f1 = X4[row * 64 + gg * 2 + 1];
            float v[8] = {f0.x, f0.y, f0.z, f0.w, f1.x, f1.y, f1.z, f1.w};
            uint4 H;
            pack8h(v, H);
            *(uint4*)&smu[OFF_XH + row * 132 + gg * 4] = H;
        }
    }

    // ---- stage 1: Y[128 tok, 192] = X @ [Wa;W1]^T  (K=256 in 4 chunks) ----
    const int wm = (w & 3) * 32;
    const int wn = (w >> 2) * 48;
    float acc1[2][6][4];
    #pragma unroll
    for (int mt = 0; mt < 2; mt++)
        #pragma unroll
        for (int nb = 0; nb < 6; nb++)
            #pragma unroll
            for (int q = 0; q < 4; q++) acc1[mt][nb][q] = 0.0f;

    uint32_t aAh[2], aBh[3];
    #pragma unroll
    for (int mt = 0; mt < 2; mt++)
        aAh[mt] = sptr(&smu[OFF_XH + (wm + mt * 16 + mrow) * 132 + acolw]);
    #pragma unroll
    for (int pp = 0; pp < 3; pp++)
        aBh[pp] = sptr(&smu[OFF_WC_H + (wn + pp * 16 + nrow) * 36 + bcolw]);

    for (int c = 0; c < 4; c++) {
        if (c > 0) {
            __syncthreads();   // previous chunk's compute done before overwrite
            #pragma unroll
            for (int it = 0; it < 3; it++) {
                int idx = tid + it * 512;
                int row = idx >> 3, seg = idx & 7;
                CP16(sptr(&smu[OFF_WC_H + row * 36 + seg * 4]),
                     &g_WcH[c * 6144 + row * 32 + seg * 4]);
            }
            CP_COMMIT();
        }
        CP_WAIT0();
        __syncthreads();

        #pragma unroll
        for (int s = 0; s < 4; s++) {
            const uint32_t offA = (uint32_t)(c * 32 + s * 8) * 4;
            const uint32_t offB = (uint32_t)(s * 8) * 4;
            uint32_t ah[2][4];
            LDSM4(ah[0][0], ah[0][1], ah[0][2], ah[0][3], aAh[0] + offA);
            LDSM4(ah[1][0], ah[1][1], ah[1][2], ah[1][3], aAh[1] + offA);
            #pragma unroll
            for (int pp = 0; pp < 3; pp++) {
                uint32_t bh[4];
                LDSM4(bh[0], bh[1], bh[2], bh[3], aBh[pp] + offB);
                #pragma unroll
                for (int e = 0; e < 2; e++) {
                    const int nb = pp * 2 + e;
                    #pragma unroll
                    for (int mt = 0; mt < 2; mt++)
                        mma16(acc1[mt][nb], ah[mt], bh + e * 2);
                }
            }
        }
    }
    __syncthreads();

    // ---- write Y column-major [col][tok] (fp32) ----
    #pragma unroll
    for (int mt = 0; mt < 2; mt++)
        #pragma unroll
        for (int nb = 0; nb < 6; nb++) {
            int row = wm + mt * 16 + ty;
            int col = wn + nb * 8 + 2 * tx;
            smf[OFF_Y + col * 132 + row]           = acc1[mt][nb][0];
            smf[OFF_Y + (col + 1) * 132 + row]     = acc1[mt][nb][1];
            smf[OFF_Y + col * 132 + row + 8]       = acc1[mt][nb][2];
            smf[OFF_Y + (col + 1) * 132 + row + 8] = acc1[mt][nb][3];
        }
    __syncthreads();

    // ---- softmax: 4 threads per token; then h-convert: 4 threads per token ----
    {
        const int tok = tid >> 2;
        const int j0 = (tid & 3) * 32;
        float mx = -1e30f;
        #pragma unroll 8
        for (int j = j0; j < j0 + 32; j++)
            mx = fmaxf(mx, smf[OFF_Y + j * 132 + tok] + s_ba[j]);
        mx = fmaxf(mx, __shfl_xor_sync(0xFFFFFFFFu, mx, 1));
        mx = fmaxf(mx, __shfl_xor_sync(0xFFFFFFFFu, mx, 2));
        float ssum = 0.0f;
        #pragma unroll 8
        for (int j = j0; j < j0 + 32; j++) {
            float e = __expf(smf[OFF_Y + j * 132 + tok] + s_ba[j] - mx);
            smf[OFF_Y + j * 132 + tok] = e;
            ssum += e;
        }
        ssum += __shfl_xor_sync(0xFFFFFFFFu, ssum, 1);
        ssum += __shfl_xor_sync(0xFFFFFFFFu, ssum, 2);
        const float inv = 1.0f / ssum;
        const int wrd = tok >> 1, hf = tok & 1;
        #pragma unroll 8
        for (int j = j0; j < j0 + 32; j++) {
            unsigned short hh =
                __half_as_ushort(__float2half_rn(smf[OFF_Y + j * 132 + tok] * inv));
            st16s(smu, OFF_AT_H + j * 68 + wrd, hf, hh);
        }
        // h: this thread handles 16 e's of its token (2 groups of 8)
        #pragma unroll
        for (int g2 = 0; g2 < 2; g2++) {
            const int gg = (tid & 3) * 2 + g2;
            float v[8];
            #pragma unroll
            for (int q = 0; q < 8; q++) {
                int e = gg * 8 + q;
                float h = smf[OFF_Y + (128 + e) * 132 + tok] + s_b1[e];
                v[q] = (h >= 0.0f) ? h : 0.01f * h;
            }
            uint4 H;
            pack8h(v, H);
            *(uint4*)&smu[OFF_H_H + tok * 36 + gg * 4] = H;
        }
    }
    __syncthreads();

    // ---- stage 2: sq[128 tok, 64] = h @ W2^T (K=64); 16 tok x 32 f per warp ----
    const int m2 = (w & 7) * 16;
    const int nsel = w >> 3;            // 0 or 1
    float acc2[4][4];
    #pragma unroll
    for (int nb = 0; nb < 4; nb++)
        #pragma unroll
        for (int q = 0; q < 4; q++) acc2[nb][q] = 0.0f;

    {
        const uint32_t aH2h = sptr(&smu[OFF_H_H + (m2 + mrow) * 36 + acolw]);
        uint32_t aW2h[2];
        #pragma unroll
        for (int pl = 0; pl < 2; pl++)
            aW2h[pl] = sptr(&smu[OFF_W2_H + ((nsel * 2 + pl) * 16 + nrow) * 36 + bcolw]);
        #pragma unroll
        for (int s = 0; s < 4; s++) {
            const uint32_t off = (uint32_t)(s * 8) * 4;
            uint32_t ah[4];
            LDSM4(ah[0], ah[1], ah[2], ah[3], aH2h + off);
            #pragma unroll
            for (int pl = 0; pl < 2; pl++) {
                uint32_t bh[4];
                LDSM4(bh[0], bh[1], bh[2], bh[3], aW2h[pl] + off);
                #pragma unroll
                for (int e = 0; e < 2; e++)
                    mma16(acc2[pl * 2 + e], ah, bh + e * 2);
            }
        }
    }
    __syncthreads();   // all stage-2 reads of h done before sq^T overwrites it

    // ---- write sq^T [d][tok] (+b2) fp16; append ones row (d=64) ----
    #pragma unroll
    for (int nb = 0; nb < 4; nb++)
        #pragma unroll
        for (int q = 0; q < 4; q++) {
            int row = m2 + ty + ((q >> 1) << 3);             // token
            int col = nsel * 32 + nb * 8 + 2 * tx + (q & 1); // d
            unsigned short hh =
                __half_as_ushort(__float2half_rn(acc2[nb][q] + s_b2[col]));
            st16s(smu, OFF_SQ_H + col * 68 + (row >> 1), row & 1, hh);
        }
    if (tid < 128) {
        const int tok = tid, wrd = tok >> 1, hf = tok & 1;
        st16s(smu, OFF_SQ_H + 64 * 68 + wrd, hf, (unsigned short)0x3C00);  // fp16 1.0
        #pragma unroll
        for (int rr = 65; rr < 72; rr++)
            st16s(smu, OFF_SQ_H + rr * 68 + wrd, hf, 0);
    }
    __syncthreads();

    // ---- stage 3: D3[128 cl, 72] = assign^T @ [sq | 1]  (K=128 tokens) ----
    float acc3[4][4];
    float acc3m[4];
    #pragma unroll
    for (int nb = 0; nb < 4; nb++)
        #pragma unroll
        for (int q = 0; q < 4; q++) acc3[nb][q] = 0.0f;
    #pragma unroll
    for (int q = 0; q < 4; q++) acc3m[q] = 0.0f;

    {
        const uint32_t aA3h = sptr(&smu[OFF_AT_H + (m2 + mrow) * 68 + acolw]);
        uint32_t aB3h[2];
        #pragma unroll
        for (int pl = 0; pl < 2; pl++)
            aB3h[pl] = sptr(&smu[OFF_SQ_H + ((nsel * 2 + pl) * 16 + nrow) * 68 + bcolw]);
        const int mat2 = (lane >> 3) & 1;
        const uint32_t aB9h = sptr(&smu[OFF_SQ_H + (64 + rowq) * 68 + mat2 * 4]);

        #pragma unroll
        for (int s = 0; s < 8; s++) {
            const uint32_t off = (uint32_t)(s * 8) * 4;
            uint32_t ah[4];
            LDSM4(ah[0], ah[1], ah[2], ah[3], aA3h + off);
            #pragma unroll
            for (int pl = 0; pl < 2; pl++) {
                uint32_t bh[4];
                LDSM4(bh[0], bh[1], bh[2], bh[3], aB3h[pl] + off);
                #pragma unroll
                for (int e = 0; e < 2; e++)
                    mma16(acc3[pl * 2 + e], ah, bh + e * 2);
            }
            if (nsel) {
                uint32_t b9h[2];
                LDSM2(b9h[0], b9h[1], aB9h + off);
                mma16(acc3m, ah, b9h);
            }
        }
    }

    // ---- epilogue: atomics ----
    {
        const size_t base0 = ((size_t)b * Kk + m2 + ty) * Dc;
        #pragma unroll
        for (int nb = 0; nb < 4; nb++) {
            int d0 = nsel * 32 + nb * 8 + 2 * tx;
            atomicAdd(&g_agg[base0 + d0],              acc3[nb][0]);
            atomicAdd(&g_agg[base0 + d0 + 1],          acc3[nb][1]);
            atomicAdd(&g_agg[base0 + 8 * Dc + d0],     acc3[nb][2]);
            atomicAdd(&g_agg[base0 + 8 * Dc + d0 + 1], acc3[nb][3]);
        }
        if (nsel && tx == 0) {
            atomicAdd(&g_mass[b * Kk + m2 + ty],     acc3m[0]);
            atomicAdd(&g_mass[b * Kk + m2 + ty + 8], acc3m[2]);
        }
    }
}

// ---------------- finalize, pass 1: vlad + partial sum-of-squares ----------------
__global__ void __launch_bounds__(256) k_vlad(const float* __restrict__ centroid,
                                              float* __restrict__ out) {
    const int b = blockIdx.x;
    const int seg = blockIdx.y;
    const int i = seg * 1024 + threadIdx.x * 4;
    const size_t gi = (size_t)b * (Kk * Dc) + i;
    const int k = i >> 6;
    const float m = g_mass[b * Kk + k];
    float4 a = *(const float4*)&g_agg[gi];
    float4 c = *(const float4*)&centroid[i];
    float4 v;
    v.x = a.x - m * c.x;
    v.y = a.y - m * c.y;
    v.z = a.z - m * c.z;
    v.w = a.w - m * c.w;
    *(float4*)&out[gi] = v;
    float ss = v.x * v.x + v.y * v.y + v.z * v.z + v.w * v.w;
    #pragma unroll
    for (int d = 16; d > 0; d >>= 1) ss += __shfl_xor_sync(0xFFFFFFFFu, ss, d);
    if ((threadIdx.x & 31) == 0) atomicAdd(&g_ss[b], ss);
}

// ---------------- finalize, pass 2: scale by 1/max(norm, eps) ----------------
__global__ void __launch_bounds__(256) k_scale(float* __restrict__ out) {
    const int b = blockIdx.x;
    const float n = sqrtf(g_ss[b]);
    const float inv = 1.0f / fmaxf(n, 1e-12f);
    const int i = blockIdx.y * 1024 + threadIdx.x * 4;
    const size_t gi = (size_t)b * (Kk * Dc) + i;
    float4 v = *(float4*)&out[gi];
    v.x *= inv; v.y *= inv; v.z *= inv; v.w *= inv;
    *(float4*)&out[gi] = v;
}

// ---------------- launch ----------------
extern "C" void kernel_launch(void* const* d_in, const int* in_sizes, int n_in,
                              void* d_out, int out_size) {
    const float* X        = (const float*)d_in[0];
    const float* W1       = (const float*)d_in[1];
    const float* b1       = (const float*)d_in[2];
    const float* W2       = (const float*)d_in[3];
    const float* b2       = (const float*)d_in[4];
    const float* Wa       = (const float*)d_in[5];
    const float* ba       = (const float*)d_in[6];
    const float* centroid = (const float*)d_in[7];
    float* out = (float*)d_out;

    cudaFuncSetAttribute(k_fused, cudaFuncAttributeMaxDynamicSharedMemorySize,
                         SMEM_WORDS * 4);

    k_setup<<<1041, 256>>>(W1, W2, Wa);
    k_fused<<<1024, 512, SMEM_WORDS * 4>>>(X, b1, b2, ba);
    dim3 gn(Bb, 8);
    k_vlad<<<gn, 256>>>(centroid, out);
    k_scale<<<gn, 256>>>(out);
}